// round 11
// baseline (speedup 1.0000x reference)
#include <cuda_runtime.h>
#include <cuda_bf16.h>
#include <math.h>
#include <stdint.h>

// ----------------------------------------------------------------------------
// Problem constants
// ----------------------------------------------------------------------------
#define NN      50000
#define EE      800000
#define NEDGE   (EE + NN)       // with self loops = 850000
#define NGRAPH  64
#define HC12    256
#define HC3     64
#define NEG_SLOPE 0.2f
#define EPSV    1e-16f

// ----------------------------------------------------------------------------
// Device scratch
// ----------------------------------------------------------------------------
__device__ __align__(256) float g_h   [(size_t)NN * HC12];
__device__ __align__(256) float g_agg [(size_t)NN * HC12];
__device__ __align__(256) float g_als [NN * 4];
__device__ __align__(256) float g_ald [NN * 4];
__device__ __align__(256) int   g_src [NEDGE];
__device__ __align__(256) int   g_dst [NEDGE];
__device__ __align__(256) int   g_off [NN + 1];
__device__ __align__(256) int   g_cur [NN];
__device__ __align__(256) int   g_csr [NEDGE];
__device__ __align__(256) int   g_batch[NN];
__device__ __align__(256) float g_pool[NGRAPH * HC3];
__device__ __align__(256) float g_cnt [NGRAPH];
__device__ float g_maxv[6];     // (maxs, maxd) per layer
__device__ int   g_is64;

// ----------------------------------------------------------------------------
// Helpers
// ----------------------------------------------------------------------------
__device__ __forceinline__ float lrelu(float x) {
    return x >= 0.f ? x : NEG_SLOPE * x;
}
__device__ __forceinline__ void atomicMaxF(float* addr, float v) {
    if (v >= 0.f) atomicMax((int*)addr, __float_as_int(v));
    else          atomicMin((unsigned int*)addr, __float_as_uint(v));
}

// tf32 split: x -> hi (rna-rounded tf32) and lo (residual as tf32), packed
__device__ __forceinline__ uint2 split_tf32_p(float x) {
    uint32_t h;
    asm("cvt.rna.tf32.f32 %0, %1;" : "=r"(h) : "f"(x));
    float r = x - __uint_as_float(h);
    uint32_t l;
    asm("cvt.rna.tf32.f32 %0, %1;" : "=r"(l) : "f"(r));
    return make_uint2(h, l);
}

__device__ __forceinline__ void mma_tf32(float* c, const uint32_t* a,
                                         uint32_t b0, uint32_t b1) {
    asm volatile(
        "mma.sync.aligned.m16n8k8.row.col.f32.tf32.tf32.f32 "
        "{%0,%1,%2,%3}, {%4,%5,%6,%7}, {%8,%9}, {%0,%1,%2,%3};"
        : "+f"(c[0]), "+f"(c[1]), "+f"(c[2]), "+f"(c[3])
        : "r"(a[0]), "r"(a[1]), "r"(a[2]), "r"(a[3]), "r"(b0), "r"(b1));
}

// ----------------------------------------------------------------------------
// Dtype probe + CSR build
// ----------------------------------------------------------------------------
__global__ void detect_dtype(const unsigned int* __restrict__ w) {
    if (threadIdx.x == 0 && blockIdx.x == 0) {
        int all0 = 1;
        for (int i = 1; i < 128; i += 2)
            if (w[i] != 0u) { all0 = 0; break; }
        g_is64 = all0;
    }
    if (blockIdx.x == 0 && threadIdx.x < 6)
        g_maxv[threadIdx.x] = -INFINITY;
}

__global__ void zero_i(int* __restrict__ p, int n) {
    int i = blockIdx.x * blockDim.x + threadIdx.x;
    if (i < n) p[i] = 0;
}

__global__ void conv_edges(const void* __restrict__ ei_raw,
                           int* __restrict__ src, int* __restrict__ dst,
                           int* __restrict__ off) {
    int i = blockIdx.x * blockDim.x + threadIdx.x;
    if (i >= NEDGE) return;
    int sv, dv;
    if (i >= EE) {
        sv = dv = i - EE;
    } else if (g_is64) {
        const long long* e = (const long long*)ei_raw;
        sv = (int)e[i];
        dv = (int)e[EE + i];
    } else {
        const int* e = (const int*)ei_raw;
        sv = e[i];
        dv = e[EE + i];
    }
    src[i] = sv;
    dst[i] = dv;
    atomicAdd(&off[dv + 1], 1);
}

__global__ void conv_batch(const void* __restrict__ b_raw, int* __restrict__ bo) {
    int i = blockIdx.x * blockDim.x + threadIdx.x;
    if (i >= NN) return;
    bo[i] = g_is64 ? (int)((const long long*)b_raw)[i] : ((const int*)b_raw)[i];
}

__global__ void scan_k(int* __restrict__ a, int n) {
    __shared__ int warp_sums[32];
    __shared__ int carry_s;
    int tid = threadIdx.x, lane = tid & 31, wid = tid >> 5;
    if (tid == 0) carry_s = 0;
    __syncthreads();
    for (int base = 0; base < n; base += 1024) {
        int idx = base + tid;
        int v = (idx < n) ? a[idx] : 0;
#pragma unroll
        for (int off = 1; off < 32; off <<= 1) {
            int t = __shfl_up_sync(0xffffffffu, v, off);
            if (lane >= off) v += t;
        }
        if (lane == 31) warp_sums[wid] = v;
        __syncthreads();
        if (wid == 0) {
            int w = warp_sums[lane];
#pragma unroll
            for (int off = 1; off < 32; off <<= 1) {
                int t = __shfl_up_sync(0xffffffffu, w, off);
                if (lane >= off) w += t;
            }
            warp_sums[lane] = w;
        }
        __syncthreads();
        int add = (wid > 0 ? warp_sums[wid - 1] : 0) + carry_s;
        if (idx < n) a[idx] = v + add;
        int total = warp_sums[31];
        __syncthreads();
        if (tid == 0) carry_s += total;
        __syncthreads();
    }
}

__global__ void set_cursors(const int* __restrict__ off, int* __restrict__ cur) {
    int i = blockIdx.x * blockDim.x + threadIdx.x;
    if (i < NN) cur[i] = off[i];
}

__global__ void scatter_csr(const int* __restrict__ src, const int* __restrict__ dst,
                            int* __restrict__ cur, int* __restrict__ csr) {
    int i = blockIdx.x * blockDim.x + threadIdx.x;
    if (i >= NEDGE) return;
    int pos = atomicAdd(&cur[dst[i]], 1);
    csr[pos] = src[i];
}

// ----------------------------------------------------------------------------
// 3xTF32 tensor-core GEMM, v2:
//  - hi/lo packed as uint2 in smem (LDS.64 fragment loads, half the LDS count;
//    row stride ≡ 8 banks mod 32 -> conflict-free per 16-lane phase)
//  - register prefetch of next K-tile (global latency overlaps MMA compute)
//  - fused attention-dot epilogue + per-layer global-max side reduction
// ----------------------------------------------------------------------------
template <int BN, int H>
__global__ __launch_bounds__(256, 2)
void mma_gemm_fused(const float* __restrict__ A, const float* __restrict__ B,
                    float* __restrict__ C, int M, int K, int Ncols,
                    const float* __restrict__ a_src, const float* __restrict__ a_dst,
                    float* __restrict__ als, float* __restrict__ ald, int layer) {
    const int BM = 128, BK = 16;
    const int WARPS_N = BN / 64;
    const int WARPS_M = 8 / WARPS_N;
    const int WROWS = BM / WARPS_M;      // 32 or 16
    const int MT = WROWS / 16;           // 2 or 1
    const int AS2 = BM + 4;              // uint2 stride: (BM+4)*2 words ≡ 8 mod 32
    const int BS2 = BN + 4;

    __shared__ uint2 As[BK][AS2];
    __shared__ uint2 Bs[BK][BS2];
    __shared__ float smax1[8], smax2[8];

    int tid = threadIdx.x;
    int wid = tid >> 5;
    int lane = tid & 31;
    int lm = lane >> 2;
    int lk = lane & 3;

    int warpN = wid % WARPS_N;
    int warpM = wid / WARPS_N;

    int mBlock = blockIdx.x * BM;
    int nBlock = blockIdx.y * BN;

    float c[MT][8][4];
#pragma unroll
    for (int i = 0; i < MT; i++)
#pragma unroll
        for (int j = 0; j < 8; j++)
#pragma unroll
            for (int q = 0; q < 4; q++) c[i][j][q] = 0.f;

    int aRow = tid >> 1;
    int aColB = (tid & 1) * 8;
    int gr = mBlock + aRow;
    bool aAct = (gr < M);

    // B load mapping
    int bRow  = (BN == 128) ? (tid >> 5) : (tid >> 4);
    int bCol4 = (BN == 128) ? (tid & 31) : (tid & 15);

    // ---- prefetch tile 0 ----
    float4 pa0, pa1, pb0, pb1;
    {
        pa0 = pa1 = make_float4(0.f, 0.f, 0.f, 0.f);
        if (aAct) {
            const float* ap = A + (size_t)gr * K + aColB;
            pa0 = *(const float4*)ap;
            pa1 = *(const float4*)(ap + 4);
        }
        pb0 = *(const float4*)(B + (size_t)bRow * Ncols + nBlock + bCol4 * 4);
        if (BN == 128)
            pb1 = *(const float4*)(B + (size_t)(bRow + 8) * Ncols + nBlock + bCol4 * 4);
    }

    for (int k0 = 0; k0 < K; k0 += BK) {
        // ---- store prefetched tile to smem (with tf32 split) ----
        {
            float av[8] = {pa0.x, pa0.y, pa0.z, pa0.w, pa1.x, pa1.y, pa1.z, pa1.w};
#pragma unroll
            for (int q = 0; q < 8; q++)
                As[aColB + q][aRow] = split_tf32_p(av[q]);

            float bv0[4] = {pb0.x, pb0.y, pb0.z, pb0.w};
#pragma unroll
            for (int q = 0; q < 4; q++)
                Bs[bRow][bCol4 * 4 + q] = split_tf32_p(bv0[q]);
            if (BN == 128) {
                float bv1[4] = {pb1.x, pb1.y, pb1.z, pb1.w};
#pragma unroll
                for (int q = 0; q < 4; q++)
                    Bs[bRow + 8][bCol4 * 4 + q] = split_tf32_p(bv1[q]);
            }
        }
        __syncthreads();

        // ---- prefetch next tile (overlaps compute below) ----
        int kn = k0 + BK;
        if (kn < K) {
            pa0 = pa1 = make_float4(0.f, 0.f, 0.f, 0.f);
            if (aAct) {
                const float* ap = A + (size_t)gr * K + kn + aColB;
                pa0 = *(const float4*)ap;
                pa1 = *(const float4*)(ap + 4);
            }
            pb0 = *(const float4*)(B + (size_t)(kn + bRow) * Ncols + nBlock + bCol4 * 4);
            if (BN == 128)
                pb1 = *(const float4*)(B + (size_t)(kn + bRow + 8) * Ncols + nBlock + bCol4 * 4);
        }

        // ---- compute: 2 k8-steps ----
#pragma unroll
        for (int kk = 0; kk < BK; kk += 8) {
            uint2 af[MT][4];
#pragma unroll
            for (int i = 0; i < MT; i++) {
                int m0 = warpM * WROWS + i * 16 + lm;
                af[i][0] = As[kk + lk][m0];
                af[i][1] = As[kk + lk][m0 + 8];
                af[i][2] = As[kk + lk + 4][m0];
                af[i][3] = As[kk + lk + 4][m0 + 8];
            }
#pragma unroll
            for (int j = 0; j < 8; j++) {
                int n0 = warpN * 64 + j * 8 + lm;
                uint2 bf0 = Bs[kk + lk][n0];
                uint2 bf1 = Bs[kk + lk + 4][n0];
#pragma unroll
                for (int i = 0; i < MT; i++) {
                    uint32_t ah[4] = {af[i][0].x, af[i][1].x, af[i][2].x, af[i][3].x};
                    uint32_t al[4] = {af[i][0].y, af[i][1].y, af[i][2].y, af[i][3].y};
                    mma_tf32(c[i][j], ah, bf0.x, bf1.x);
                    mma_tf32(c[i][j], ah, bf0.y, bf1.y);
                    mma_tf32(c[i][j], al, bf0.x, bf1.x);
                }
            }
        }
        __syncthreads();
    }

    // ---- epilogue: store C + fused attention dots + global-max side band ----
    int head_base = nBlock + warpN * 64;
    int head = head_base >> 6;

    float wm1 = -INFINITY, wm2 = -INFINITY;

#pragma unroll
    for (int i = 0; i < MT; i++) {
        int r0 = mBlock + warpM * WROWS + i * 16 + lm;
        int r1 = r0 + 8;
        float d1a = 0.f, d2a = 0.f, d1b = 0.f, d2b = 0.f;
#pragma unroll
        for (int j = 0; j < 8; j++) {
            int colg = head_base + j * 8 + lk * 2;
            float as0 = a_src[colg], as1 = a_src[colg + 1];
            float ad0 = a_dst[colg], ad1 = a_dst[colg + 1];
            float* cc = c[i][j];
            d1a += cc[0] * as0 + cc[1] * as1;
            d2a += cc[0] * ad0 + cc[1] * ad1;
            d1b += cc[2] * as0 + cc[3] * as1;
            d2b += cc[2] * ad0 + cc[3] * ad1;
            if (r0 < M) *(float2*)&C[(size_t)r0 * Ncols + colg] = make_float2(cc[0], cc[1]);
            if (r1 < M) *(float2*)&C[(size_t)r1 * Ncols + colg] = make_float2(cc[2], cc[3]);
        }
#pragma unroll
        for (int off = 1; off <= 2; off <<= 1) {
            d1a += __shfl_xor_sync(0xffffffffu, d1a, off);
            d2a += __shfl_xor_sync(0xffffffffu, d2a, off);
            d1b += __shfl_xor_sync(0xffffffffu, d1b, off);
            d2b += __shfl_xor_sync(0xffffffffu, d2b, off);
        }
        if (r0 < M) { wm1 = fmaxf(wm1, d1a); wm2 = fmaxf(wm2, d2a); }
        if (r1 < M) { wm1 = fmaxf(wm1, d1b); wm2 = fmaxf(wm2, d2b); }
        if (lk == 0) {
            if (r0 < M) { als[r0 * H + head] = d1a; ald[r0 * H + head] = d2a; }
            if (r1 < M) { als[r1 * H + head] = d1b; ald[r1 * H + head] = d2b; }
        }
    }

#pragma unroll
    for (int off = 16; off > 0; off >>= 1) {
        wm1 = fmaxf(wm1, __shfl_xor_sync(0xffffffffu, wm1, off));
        wm2 = fmaxf(wm2, __shfl_xor_sync(0xffffffffu, wm2, off));
    }
    if (lane == 0) { smax1[wid] = wm1; smax2[wid] = wm2; }
    __syncthreads();
    if (tid == 0) {
        float m1 = smax1[0], m2 = smax2[0];
#pragma unroll
        for (int i = 1; i < 8; i++) {
            m1 = fmaxf(m1, smax1[i]);
            m2 = fmaxf(m2, smax2[i]);
        }
        atomicMaxF(&g_maxv[2 * layer], m1);
        atomicMaxF(&g_maxv[2 * layer + 1], m2);
    }
}

// ----------------------------------------------------------------------------
// CSR gather-aggregate, H=4 C=64. Warp per dst node; global-shift softmax.
// Unroll-2 gather + fused normalize/bias/relu.
// ----------------------------------------------------------------------------
__global__ void gat_agg4(const int* __restrict__ off, const int* __restrict__ csr,
                         const float* __restrict__ h,
                         const float* __restrict__ als, const float* __restrict__ ald,
                         const float4* __restrict__ bias, float* __restrict__ out,
                         int layer) {
    int node = (blockIdx.x * blockDim.x + threadIdx.x) >> 5;
    int lane = threadIdx.x & 31;
    if (node >= NN) return;

    float Mg = fmaxf(0.f, g_maxv[2 * layer] + g_maxv[2 * layer + 1]);
    int head = lane >> 3;
    float aldv = ald[node * 4 + head];

    float4 acc0 = make_float4(0.f, 0.f, 0.f, 0.f);
    float4 acc1 = make_float4(0.f, 0.f, 0.f, 0.f);
    float ssum = 0.f;

    int beg = off[node], end = off[node + 1];
    int i = beg;
    for (; i + 1 < end; i += 2) {
        int s0 = csr[i], s1 = csr[i + 1];
        float wt0 = __expf(lrelu(als[s0 * 4 + head] + aldv) - Mg);
        float wt1 = __expf(lrelu(als[s1 * 4 + head] + aldv) - Mg);
        const float4* h0 = (const float4*)(h + (size_t)s0 * 256 + lane * 8);
        const float4* h1 = (const float4*)(h + (size_t)s1 * 256 + lane * 8);
        float4 v00 = h0[0], v01 = h0[1];
        float4 v10 = h1[0], v11 = h1[1];
        ssum += wt0 + wt1;
        acc0.x += wt0 * v00.x + wt1 * v10.x;
        acc0.y += wt0 * v00.y + wt1 * v10.y;
        acc0.z += wt0 * v00.z + wt1 * v10.z;
        acc0.w += wt0 * v00.w + wt1 * v10.w;
        acc1.x += wt0 * v01.x + wt1 * v11.x;
        acc1.y += wt0 * v01.y + wt1 * v11.y;
        acc1.z += wt0 * v01.z + wt1 * v11.z;
        acc1.w += wt0 * v01.w + wt1 * v11.w;
    }
    if (i < end) {
        int s0 = csr[i];
        float wt0 = __expf(lrelu(als[s0 * 4 + head] + aldv) - Mg);
        const float4* h0 = (const float4*)(h + (size_t)s0 * 256 + lane * 8);
        float4 v00 = h0[0], v01 = h0[1];
        ssum += wt0;
        acc0.x += wt0 * v00.x; acc0.y += wt0 * v00.y;
        acc0.z += wt0 * v00.z; acc0.w += wt0 * v00.w;
        acc1.x += wt0 * v01.x; acc1.y += wt0 * v01.y;
        acc1.z += wt0 * v01.z; acc1.w += wt0 * v01.w;
    }

    float inv = 1.f / (ssum + EPSV);
    float4 b0 = bias[lane * 2];
    float4 b1 = bias[lane * 2 + 1];
    float4 r0, r1;
    r0.x = fmaxf(acc0.x * inv + b0.x, 0.f);
    r0.y = fmaxf(acc0.y * inv + b0.y, 0.f);
    r0.z = fmaxf(acc0.z * inv + b0.z, 0.f);
    r0.w = fmaxf(acc0.w * inv + b0.w, 0.f);
    r1.x = fmaxf(acc1.x * inv + b1.x, 0.f);
    r1.y = fmaxf(acc1.y * inv + b1.y, 0.f);
    r1.z = fmaxf(acc1.z * inv + b1.z, 0.f);
    r1.w = fmaxf(acc1.w * inv + b1.w, 0.f);
    float4* op = (float4*)(out + (size_t)node * 256 + lane * 8);
    op[0] = r0;
    op[1] = r1;
}

// CSR gather-aggregate, H=1 C=64 (unroll-2)
__global__ void gat_agg1(const int* __restrict__ off, const int* __restrict__ csr,
                         const float* __restrict__ h,
                         const float* __restrict__ als, const float* __restrict__ ald,
                         float* __restrict__ out, int layer) {
    int node = (blockIdx.x * blockDim.x + threadIdx.x) >> 5;
    int lane = threadIdx.x & 31;
    if (node >= NN) return;

    float Mg = fmaxf(0.f, g_maxv[2 * layer] + g_maxv[2 * layer + 1]);
    float aldv = ald[node];

    float2 acc = make_float2(0.f, 0.f);
    float ssum = 0.f;

    int beg = off[node], end = off[node + 1];
    int i = beg;
    for (; i + 1 < end; i += 2) {
        int s0 = csr[i], s1 = csr[i + 1];
        float wt0 = __expf(lrelu(als[s0] + aldv) - Mg);
        float wt1 = __expf(lrelu(als[s1] + aldv) - Mg);
        float2 v0 = *(const float2*)(h + (size_t)s0 * 64 + lane * 2);
        float2 v1 = *(const float2*)(h + (size_t)s1 * 64 + lane * 2);
        ssum += wt0 + wt1;
        acc.x += wt0 * v0.x + wt1 * v1.x;
        acc.y += wt0 * v0.y + wt1 * v1.y;
    }
    if (i < end) {
        int s0 = csr[i];
        float wt0 = __expf(lrelu(als[s0] + aldv) - Mg);
        float2 v0 = *(const float2*)(h + (size_t)s0 * 64 + lane * 2);
        ssum += wt0;
        acc.x += wt0 * v0.x;
        acc.y += wt0 * v0.y;
    }

    float inv = 1.f / (ssum + EPSV);
    *(float2*)(out + (size_t)node * 64 + lane * 2) =
        make_float2(acc.x * inv, acc.y * inv);
}

// ----------------------------------------------------------------------------
// Pool + final
// ----------------------------------------------------------------------------
__global__ void zero_f4(float4* __restrict__ p, int n4) {
    int i = blockIdx.x * blockDim.x + threadIdx.x;
    int stride = gridDim.x * blockDim.x;
    float4 z = make_float4(0.f, 0.f, 0.f, 0.f);
    for (; i < n4; i += stride) p[i] = z;
}

__global__ void counts_k(const int* __restrict__ batch, float* __restrict__ cnt) {
    int g = threadIdx.x;
    if (g >= NGRAPH) return;
    int lo = 0, hi = NN;
    while (lo < hi) { int mid = (lo + hi) >> 1; if (batch[mid] < g) lo = mid + 1; else hi = mid; }
    int a = lo;
    lo = 0; hi = NN;
    while (lo < hi) { int mid = (lo + hi) >> 1; if (batch[mid] < g + 1) lo = mid + 1; else hi = mid; }
    cnt[g] = (float)(lo - a);
}

__global__ void pool_sum(const float* __restrict__ h, const int* __restrict__ batch,
                         float* __restrict__ pool) {
    int c = threadIdx.x & 63;
    int r = threadIdx.x >> 6;
    int start = blockIdx.x * 1024;
    int end = start + 1024;
    if (end > NN) end = NN;
    int cur = -1;
    float acc = 0.f;
    for (int nd = start + r; nd < end; nd += 4) {
        int g = batch[nd];
        if (g != cur) {
            if (cur >= 0) atomicAdd(&pool[cur * 64 + c], acc);
            cur = g;
            acc = 0.f;
        }
        acc += h[(size_t)nd * 64 + c];
    }
    if (cur >= 0) atomicAdd(&pool[cur * 64 + c], acc);
}

__global__ void final_k(const float* __restrict__ pool, const float* __restrict__ cnt,
                        const float* __restrict__ b3,
                        const float* __restrict__ linW, const float* __restrict__ linb,
                        float* __restrict__ out) {
    int g = blockIdx.x;
    int j = threadIdx.x;
    __shared__ float mean[64];
    float cc = fmaxf(cnt[g], 1.f);
    mean[j] = pool[g * 64 + j] / cc + b3[j];
    __syncthreads();
    float acc = 0.f;
#pragma unroll
    for (int k = 0; k < 64; k++) acc += mean[k] * linW[k * 64 + j];
    out[g * 64 + j] = acc + linb[j];
}

// ----------------------------------------------------------------------------
// Host launcher (layer-1 GEMM kept at the profiled stream slot)
// ----------------------------------------------------------------------------
extern "C" void kernel_launch(void* const* d_in, const int* in_sizes, int n_in,
                              void* d_out, int out_size) {
    const float* x     = (const float*)d_in[0];
    const void*  ei    = d_in[1];
    const void*  batch = d_in[3];
    const float* W1  = (const float*)d_in[4];
    const float* a1s = (const float*)d_in[5];
    const float* a1d = (const float*)d_in[6];
    const float* b1  = (const float*)d_in[7];
    const float* W2  = (const float*)d_in[8];
    const float* a2s = (const float*)d_in[9];
    const float* a2d = (const float*)d_in[10];
    const float* b2  = (const float*)d_in[11];
    const float* W3  = (const float*)d_in[12];
    const float* a3s = (const float*)d_in[13];
    const float* a3d = (const float*)d_in[14];
    const float* b3  = (const float*)d_in[15];
    const float* lW  = (const float*)d_in[16];
    const float* lb  = (const float*)d_in[17];
    float* out = (float*)d_out;

    float *p_h, *p_agg, *p_als, *p_ald, *p_pool, *p_cnt;
    int *p_src, *p_dst, *p_off, *p_cur, *p_csr, *p_batch;
    cudaGetSymbolAddress((void**)&p_h,    g_h);
    cudaGetSymbolAddress((void**)&p_agg,  g_agg);
    cudaGetSymbolAddress((void**)&p_als,  g_als);
    cudaGetSymbolAddress((void**)&p_ald,  g_ald);
    cudaGetSymbolAddress((void**)&p_src,  g_src);
    cudaGetSymbolAddress((void**)&p_dst,  g_dst);
    cudaGetSymbolAddress((void**)&p_off,  g_off);
    cudaGetSymbolAddress((void**)&p_cur,  g_cur);
    cudaGetSymbolAddress((void**)&p_csr,  g_csr);
    cudaGetSymbolAddress((void**)&p_batch,g_batch);
    cudaGetSymbolAddress((void**)&p_pool, g_pool);
    cudaGetSymbolAddress((void**)&p_cnt,  g_cnt);

    const int TB = 256;
    const int mTiles = (NN + 127) / 128;
    const int nodeWarpBlocks = (NN * 32 + TB - 1) / TB;

    detect_dtype<<<1, 32>>>((const unsigned int*)ei);                        // 0
    zero_i<<<(NN + 1 + TB - 1) / TB, TB>>>(p_off, NN + 1);                   // 1
    conv_edges<<<(NEDGE + TB - 1) / TB, TB>>>(ei, p_src, p_dst, p_off);      // 2

    // pos 3: layer-1 GEMM (profiled slot)
    {
        dim3 grid(mTiles, HC12 / 128);
        mma_gemm_fused<128, 4><<<grid, TB>>>(x, W1, p_h, NN, 128, HC12,
                                             a1s, a1d, p_als, p_ald, 0);     // 3
    }

    scan_k<<<1, 1024>>>(p_off, NN + 1);                                      // 4
    set_cursors<<<(NN + TB - 1) / TB, TB>>>(p_off, p_cur);                   // 5
    scatter_csr<<<(NEDGE + TB - 1) / TB, TB>>>(p_src, p_dst, p_cur, p_csr);  // 6
    conv_batch<<<(NN + TB - 1) / TB, TB>>>(batch, p_batch);                  // 7

    // ================= Layer 1 aggregation =================
    gat_agg4<<<nodeWarpBlocks, TB>>>(p_off, p_csr, p_h, p_als, p_ald,
                                     (const float4*)b1, p_agg, 0);

    // ================= Layer 2 =================
    {
        dim3 grid(mTiles, HC12 / 128);
        mma_gemm_fused<128, 4><<<grid, TB>>>(p_agg, W2, p_h, NN, HC12, HC12,
                                             a2s, a2d, p_als, p_ald, 1);
        gat_agg4<<<nodeWarpBlocks, TB>>>(p_off, p_csr, p_h, p_als, p_ald,
                                         (const float4*)b2, p_agg, 1);
    }

    // ================= Layer 3 =================
    {
        dim3 grid(mTiles, 1);
        mma_gemm_fused<64, 1><<<grid, TB>>>(p_agg, W3, p_h, NN, HC12, HC3,
                                            a3s, a3d, p_als, p_ald, 2);
        gat_agg1<<<nodeWarpBlocks, TB>>>(p_off, p_csr, p_h, p_als, p_ald, p_agg, 2);
    }

    // ================= Pool + final linear =================
    zero_f4<<<4, 64>>>((float4*)p_pool, NGRAPH * HC3 / 4);
    counts_k<<<1, 64>>>(p_batch, p_cnt);
    pool_sum<<<(NN + 1023) / 1024, 256>>>(p_agg, p_batch, p_pool);
    final_k<<<NGRAPH, 64>>>(p_pool, p_cnt, b3, lW, lb, out);
}

// round 13
// speedup vs baseline: 1.0033x; 1.0033x over previous
#include <cuda_runtime.h>
#include <cuda_bf16.h>
#include <math.h>
#include <stdint.h>

// ----------------------------------------------------------------------------
// Problem constants
// ----------------------------------------------------------------------------
#define NN      50000
#define EE      800000
#define NEDGE   (EE + NN)       // with self loops = 850000
#define NGRAPH  64
#define HC12    256
#define HC3     64
#define NEG_SLOPE 0.2f
#define EPSV    1e-16f

// ----------------------------------------------------------------------------
// Device scratch
// ----------------------------------------------------------------------------
__device__ __align__(256) float g_h   [(size_t)NN * HC12];
__device__ __align__(256) float g_agg [(size_t)NN * HC12];
__device__ __align__(256) float g_als [NN * 4];
__device__ __align__(256) float g_ald [NN * 4];
__device__ __align__(256) int   g_src [NEDGE];
__device__ __align__(256) int   g_dst [NEDGE];
__device__ __align__(256) int   g_off [NN + 1];
__device__ __align__(256) int   g_cur [NN];
__device__ __align__(256) int   g_csr [NEDGE];
__device__ __align__(256) int   g_batch[NN];
__device__ __align__(256) float g_pool[NGRAPH * HC3];
__device__ __align__(256) float g_cnt [NGRAPH];
__device__ float g_maxv[6];     // (maxs, maxd) per layer
__device__ int   g_is64;

// ----------------------------------------------------------------------------
// Helpers
// ----------------------------------------------------------------------------
__device__ __forceinline__ float lrelu(float x) {
    return x >= 0.f ? x : NEG_SLOPE * x;
}
__device__ __forceinline__ void atomicMaxF(float* addr, float v) {
    if (v >= 0.f) atomicMax((int*)addr, __float_as_int(v));
    else          atomicMin((unsigned int*)addr, __float_as_uint(v));
}

// tf32 split: x -> hi (rna-rounded tf32) and lo (residual as tf32), packed
__device__ __forceinline__ uint2 split_tf32_p(float x) {
    uint32_t h;
    asm("cvt.rna.tf32.f32 %0, %1;" : "=r"(h) : "f"(x));
    float r = x - __uint_as_float(h);
    uint32_t l;
    asm("cvt.rna.tf32.f32 %0, %1;" : "=r"(l) : "f"(r));
    return make_uint2(h, l);
}

__device__ __forceinline__ void mma_tf32(float* c, const uint32_t* a,
                                         uint32_t b0, uint32_t b1) {
    asm volatile(
        "mma.sync.aligned.m16n8k8.row.col.f32.tf32.tf32.f32 "
        "{%0,%1,%2,%3}, {%4,%5,%6,%7}, {%8,%9}, {%0,%1,%2,%3};"
        : "+f"(c[0]), "+f"(c[1]), "+f"(c[2]), "+f"(c[3])
        : "r"(a[0]), "r"(a[1]), "r"(a[2]), "r"(a[3]), "r"(b0), "r"(b1));
}

// ----------------------------------------------------------------------------
// Dtype probe + CSR build
// ----------------------------------------------------------------------------
__global__ void detect_dtype(const unsigned int* __restrict__ w) {
    if (threadIdx.x == 0 && blockIdx.x == 0) {
        int all0 = 1;
        for (int i = 1; i < 128; i += 2)
            if (w[i] != 0u) { all0 = 0; break; }
        g_is64 = all0;
    }
    if (blockIdx.x == 0 && threadIdx.x < 6)
        g_maxv[threadIdx.x] = -INFINITY;
}

__global__ void zero_i(int* __restrict__ p, int n) {
    int i = blockIdx.x * blockDim.x + threadIdx.x;
    if (i < n) p[i] = 0;
}

__global__ void conv_edges(const void* __restrict__ ei_raw,
                           int* __restrict__ src, int* __restrict__ dst,
                           int* __restrict__ off) {
    int i = blockIdx.x * blockDim.x + threadIdx.x;
    if (i >= NEDGE) return;
    int sv, dv;
    if (i >= EE) {
        sv = dv = i - EE;
    } else if (g_is64) {
        const long long* e = (const long long*)ei_raw;
        sv = (int)e[i];
        dv = (int)e[EE + i];
    } else {
        const int* e = (const int*)ei_raw;
        sv = e[i];
        dv = e[EE + i];
    }
    src[i] = sv;
    dst[i] = dv;
    atomicAdd(&off[dv + 1], 1);
}

__global__ void conv_batch(const void* __restrict__ b_raw, int* __restrict__ bo) {
    int i = blockIdx.x * blockDim.x + threadIdx.x;
    if (i >= NN) return;
    bo[i] = g_is64 ? (int)((const long long*)b_raw)[i] : ((const int*)b_raw)[i];
}

__global__ void scan_k(int* __restrict__ a, int n) {
    __shared__ int warp_sums[32];
    __shared__ int carry_s;
    int tid = threadIdx.x, lane = tid & 31, wid = tid >> 5;
    if (tid == 0) carry_s = 0;
    __syncthreads();
    for (int base = 0; base < n; base += 1024) {
        int idx = base + tid;
        int v = (idx < n) ? a[idx] : 0;
#pragma unroll
        for (int off = 1; off < 32; off <<= 1) {
            int t = __shfl_up_sync(0xffffffffu, v, off);
            if (lane >= off) v += t;
        }
        if (lane == 31) warp_sums[wid] = v;
        __syncthreads();
        if (wid == 0) {
            int w = warp_sums[lane];
#pragma unroll
            for (int off = 1; off < 32; off <<= 1) {
                int t = __shfl_up_sync(0xffffffffu, w, off);
                if (lane >= off) w += t;
            }
            warp_sums[lane] = w;
        }
        __syncthreads();
        int add = (wid > 0 ? warp_sums[wid - 1] : 0) + carry_s;
        if (idx < n) a[idx] = v + add;
        int total = warp_sums[31];
        __syncthreads();
        if (tid == 0) carry_s += total;
        __syncthreads();
    }
}

__global__ void set_cursors(const int* __restrict__ off, int* __restrict__ cur) {
    int i = blockIdx.x * blockDim.x + threadIdx.x;
    if (i < NN) cur[i] = off[i];
}

__global__ void scatter_csr(const int* __restrict__ src, const int* __restrict__ dst,
                            int* __restrict__ cur, int* __restrict__ csr) {
    int i = blockIdx.x * blockDim.x + threadIdx.x;
    if (i >= NEDGE) return;
    int pos = atomicAdd(&cur[dst[i]], 1);
    csr[pos] = src[i];
}

// ----------------------------------------------------------------------------
// 3xTF32 tensor-core GEMM, v3:
//  - hi/lo packed as uint2 in smem (LDS.64 fragment loads)
//  - ah/al unpack hoisted OUT of the j-loop (v2 regression fix: the in-loop
//    array construction generated 8x redundant MOVs -> alu pipe 34%)
//  - register prefetch of next K-tile
//  - fused attention-dot epilogue + per-layer global-max side reduction
// ----------------------------------------------------------------------------
template <int BN, int H>
__global__ __launch_bounds__(256, 2)
void mma_gemm_fused(const float* __restrict__ A, const float* __restrict__ B,
                    float* __restrict__ C, int M, int K, int Ncols,
                    const float* __restrict__ a_src, const float* __restrict__ a_dst,
                    float* __restrict__ als, float* __restrict__ ald, int layer) {
    const int BM = 128, BK = 16;
    const int WARPS_N = BN / 64;
    const int WARPS_M = 8 / WARPS_N;
    const int WROWS = BM / WARPS_M;      // 32 or 16
    const int MT = WROWS / 16;           // 2 or 1
    const int AS2 = BM + 4;              // uint2 stride
    const int BS2 = BN + 4;

    __shared__ uint2 As[BK][AS2];
    __shared__ uint2 Bs[BK][BS2];
    __shared__ float smax1[8], smax2[8];

    int tid = threadIdx.x;
    int wid = tid >> 5;
    int lane = tid & 31;
    int lm = lane >> 2;
    int lk = lane & 3;

    int warpN = wid % WARPS_N;
    int warpM = wid / WARPS_N;

    int mBlock = blockIdx.x * BM;
    int nBlock = blockIdx.y * BN;

    float c[MT][8][4];
#pragma unroll
    for (int i = 0; i < MT; i++)
#pragma unroll
        for (int j = 0; j < 8; j++)
#pragma unroll
            for (int q = 0; q < 4; q++) c[i][j][q] = 0.f;

    int aRow = tid >> 1;
    int aColB = (tid & 1) * 8;
    int gr = mBlock + aRow;
    bool aAct = (gr < M);

    int bRow  = (BN == 128) ? (tid >> 5) : (tid >> 4);
    int bCol4 = (BN == 128) ? (tid & 31) : (tid & 15);

    // ---- prefetch tile 0 ----
    float4 pa0, pa1, pb0, pb1;
    {
        pa0 = pa1 = make_float4(0.f, 0.f, 0.f, 0.f);
        if (aAct) {
            const float* ap = A + (size_t)gr * K + aColB;
            pa0 = *(const float4*)ap;
            pa1 = *(const float4*)(ap + 4);
        }
        pb0 = *(const float4*)(B + (size_t)bRow * Ncols + nBlock + bCol4 * 4);
        if (BN == 128)
            pb1 = *(const float4*)(B + (size_t)(bRow + 8) * Ncols + nBlock + bCol4 * 4);
    }

    for (int k0 = 0; k0 < K; k0 += BK) {
        // ---- store prefetched tile to smem (with tf32 split) ----
        {
            float av[8] = {pa0.x, pa0.y, pa0.z, pa0.w, pa1.x, pa1.y, pa1.z, pa1.w};
#pragma unroll
            for (int q = 0; q < 8; q++)
                As[aColB + q][aRow] = split_tf32_p(av[q]);

            float bv0[4] = {pb0.x, pb0.y, pb0.z, pb0.w};
#pragma unroll
            for (int q = 0; q < 4; q++)
                Bs[bRow][bCol4 * 4 + q] = split_tf32_p(bv0[q]);
            if (BN == 128) {
                float bv1[4] = {pb1.x, pb1.y, pb1.z, pb1.w};
#pragma unroll
                for (int q = 0; q < 4; q++)
                    Bs[bRow + 8][bCol4 * 4 + q] = split_tf32_p(bv1[q]);
            }
        }
        __syncthreads();

        // ---- prefetch next tile (overlaps compute below) ----
        int kn = k0 + BK;
        if (kn < K) {
            pa0 = pa1 = make_float4(0.f, 0.f, 0.f, 0.f);
            if (aAct) {
                const float* ap = A + (size_t)gr * K + kn + aColB;
                pa0 = *(const float4*)ap;
                pa1 = *(const float4*)(ap + 4);
            }
            pb0 = *(const float4*)(B + (size_t)(kn + bRow) * Ncols + nBlock + bCol4 * 4);
            if (BN == 128)
                pb1 = *(const float4*)(B + (size_t)(kn + bRow + 8) * Ncols + nBlock + bCol4 * 4);
        }

        // ---- compute: 2 k8-steps ----
#pragma unroll
        for (int kk = 0; kk < BK; kk += 8) {
            // load + unpack A fragments ONCE per kk-step
            uint32_t ah[MT][4], al[MT][4];
#pragma unroll
            for (int i = 0; i < MT; i++) {
                int m0 = warpM * WROWS + i * 16 + lm;
                uint2 a0 = As[kk + lk][m0];
                uint2 a1 = As[kk + lk][m0 + 8];
                uint2 a2 = As[kk + lk + 4][m0];
                uint2 a3 = As[kk + lk + 4][m0 + 8];
                ah[i][0] = a0.x; ah[i][1] = a1.x; ah[i][2] = a2.x; ah[i][3] = a3.x;
                al[i][0] = a0.y; al[i][1] = a1.y; al[i][2] = a2.y; al[i][3] = a3.y;
            }
#pragma unroll
            for (int j = 0; j < 8; j++) {
                int n0 = warpN * 64 + j * 8 + lm;
                uint2 bf0 = Bs[kk + lk][n0];
                uint2 bf1 = Bs[kk + lk + 4][n0];
#pragma unroll
                for (int i = 0; i < MT; i++) {
                    mma_tf32(c[i][j], ah[i], bf0.x, bf1.x);
                    mma_tf32(c[i][j], ah[i], bf0.y, bf1.y);
                    mma_tf32(c[i][j], al[i], bf0.x, bf1.x);
                }
            }
        }
        __syncthreads();
    }

    // ---- epilogue: store C + fused attention dots + global-max side band ----
    int head_base = nBlock + warpN * 64;
    int head = head_base >> 6;

    float wm1 = -INFINITY, wm2 = -INFINITY;

#pragma unroll
    for (int i = 0; i < MT; i++) {
        int r0 = mBlock + warpM * WROWS + i * 16 + lm;
        int r1 = r0 + 8;
        float d1a = 0.f, d2a = 0.f, d1b = 0.f, d2b = 0.f;
#pragma unroll
        for (int j = 0; j < 8; j++) {
            int colg = head_base + j * 8 + lk * 2;
            float as0 = a_src[colg], as1 = a_src[colg + 1];
            float ad0 = a_dst[colg], ad1 = a_dst[colg + 1];
            float* cc = c[i][j];
            d1a += cc[0] * as0 + cc[1] * as1;
            d2a += cc[0] * ad0 + cc[1] * ad1;
            d1b += cc[2] * as0 + cc[3] * as1;
            d2b += cc[2] * ad0 + cc[3] * ad1;
            if (r0 < M) *(float2*)&C[(size_t)r0 * Ncols + colg] = make_float2(cc[0], cc[1]);
            if (r1 < M) *(float2*)&C[(size_t)r1 * Ncols + colg] = make_float2(cc[2], cc[3]);
        }
#pragma unroll
        for (int off = 1; off <= 2; off <<= 1) {
            d1a += __shfl_xor_sync(0xffffffffu, d1a, off);
            d2a += __shfl_xor_sync(0xffffffffu, d2a, off);
            d1b += __shfl_xor_sync(0xffffffffu, d1b, off);
            d2b += __shfl_xor_sync(0xffffffffu, d2b, off);
        }
        if (r0 < M) { wm1 = fmaxf(wm1, d1a); wm2 = fmaxf(wm2, d2a); }
        if (r1 < M) { wm1 = fmaxf(wm1, d1b); wm2 = fmaxf(wm2, d2b); }
        if (lk == 0) {
            if (r0 < M) { als[r0 * H + head] = d1a; ald[r0 * H + head] = d2a; }
            if (r1 < M) { als[r1 * H + head] = d1b; ald[r1 * H + head] = d2b; }
        }
    }

#pragma unroll
    for (int off = 16; off > 0; off >>= 1) {
        wm1 = fmaxf(wm1, __shfl_xor_sync(0xffffffffu, wm1, off));
        wm2 = fmaxf(wm2, __shfl_xor_sync(0xffffffffu, wm2, off));
    }
    if (lane == 0) { smax1[wid] = wm1; smax2[wid] = wm2; }
    __syncthreads();
    if (tid == 0) {
        float m1 = smax1[0], m2 = smax2[0];
#pragma unroll
        for (int i = 1; i < 8; i++) {
            m1 = fmaxf(m1, smax1[i]);
            m2 = fmaxf(m2, smax2[i]);
        }
        atomicMaxF(&g_maxv[2 * layer], m1);
        atomicMaxF(&g_maxv[2 * layer + 1], m2);
    }
}

// ----------------------------------------------------------------------------
// CSR gather-aggregate, H=4 C=64. Warp per dst node; global-shift softmax.
// ----------------------------------------------------------------------------
__global__ void gat_agg4(const int* __restrict__ off, const int* __restrict__ csr,
                         const float* __restrict__ h,
                         const float* __restrict__ als, const float* __restrict__ ald,
                         const float4* __restrict__ bias, float* __restrict__ out,
                         int layer) {
    int node = (blockIdx.x * blockDim.x + threadIdx.x) >> 5;
    int lane = threadIdx.x & 31;
    if (node >= NN) return;

    float Mg = fmaxf(0.f, g_maxv[2 * layer] + g_maxv[2 * layer + 1]);
    int head = lane >> 3;
    float aldv = ald[node * 4 + head];

    float4 acc0 = make_float4(0.f, 0.f, 0.f, 0.f);
    float4 acc1 = make_float4(0.f, 0.f, 0.f, 0.f);
    float ssum = 0.f;

    int beg = off[node], end = off[node + 1];
    int i = beg;
    for (; i + 1 < end; i += 2) {
        int s0 = csr[i], s1 = csr[i + 1];
        float wt0 = __expf(lrelu(als[s0 * 4 + head] + aldv) - Mg);
        float wt1 = __expf(lrelu(als[s1 * 4 + head] + aldv) - Mg);
        const float4* h0 = (const float4*)(h + (size_t)s0 * 256 + lane * 8);
        const float4* h1 = (const float4*)(h + (size_t)s1 * 256 + lane * 8);
        float4 v00 = h0[0], v01 = h0[1];
        float4 v10 = h1[0], v11 = h1[1];
        ssum += wt0 + wt1;
        acc0.x += wt0 * v00.x + wt1 * v10.x;
        acc0.y += wt0 * v00.y + wt1 * v10.y;
        acc0.z += wt0 * v00.z + wt1 * v10.z;
        acc0.w += wt0 * v00.w + wt1 * v10.w;
        acc1.x += wt0 * v01.x + wt1 * v11.x;
        acc1.y += wt0 * v01.y + wt1 * v11.y;
        acc1.z += wt0 * v01.z + wt1 * v11.z;
        acc1.w += wt0 * v01.w + wt1 * v11.w;
    }
    if (i < end) {
        int s0 = csr[i];
        float wt0 = __expf(lrelu(als[s0 * 4 + head] + aldv) - Mg);
        const float4* h0 = (const float4*)(h + (size_t)s0 * 256 + lane * 8);
        float4 v00 = h0[0], v01 = h0[1];
        ssum += wt0;
        acc0.x += wt0 * v00.x; acc0.y += wt0 * v00.y;
        acc0.z += wt0 * v00.z; acc0.w += wt0 * v00.w;
        acc1.x += wt0 * v01.x; acc1.y += wt0 * v01.y;
        acc1.z += wt0 * v01.z; acc1.w += wt0 * v01.w;
    }

    float inv = 1.f / (ssum + EPSV);
    float4 b0 = bias[lane * 2];
    float4 b1 = bias[lane * 2 + 1];
    float4 r0, r1;
    r0.x = fmaxf(acc0.x * inv + b0.x, 0.f);
    r0.y = fmaxf(acc0.y * inv + b0.y, 0.f);
    r0.z = fmaxf(acc0.z * inv + b0.z, 0.f);
    r0.w = fmaxf(acc0.w * inv + b0.w, 0.f);
    r1.x = fmaxf(acc1.x * inv + b1.x, 0.f);
    r1.y = fmaxf(acc1.y * inv + b1.y, 0.f);
    r1.z = fmaxf(acc1.z * inv + b1.z, 0.f);
    r1.w = fmaxf(acc1.w * inv + b1.w, 0.f);
    float4* op = (float4*)(out + (size_t)node * 256 + lane * 8);
    op[0] = r0;
    op[1] = r1;
}

// CSR gather-aggregate, H=1 C=64 (unroll-2)
__global__ void gat_agg1(const int* __restrict__ off, const int* __restrict__ csr,
                         const float* __restrict__ h,
                         const float* __restrict__ als, const float* __restrict__ ald,
                         float* __restrict__ out, int layer) {
    int node = (blockIdx.x * blockDim.x + threadIdx.x) >> 5;
    int lane = threadIdx.x & 31;
    if (node >= NN) return;

    float Mg = fmaxf(0.f, g_maxv[2 * layer] + g_maxv[2 * layer + 1]);
    float aldv = ald[node];

    float2 acc = make_float2(0.f, 0.f);
    float ssum = 0.f;

    int beg = off[node], end = off[node + 1];
    int i = beg;
    for (; i + 1 < end; i += 2) {
        int s0 = csr[i], s1 = csr[i + 1];
        float wt0 = __expf(lrelu(als[s0] + aldv) - Mg);
        float wt1 = __expf(lrelu(als[s1] + aldv) - Mg);
        float2 v0 = *(const float2*)(h + (size_t)s0 * 64 + lane * 2);
        float2 v1 = *(const float2*)(h + (size_t)s1 * 64 + lane * 2);
        ssum += wt0 + wt1;
        acc.x += wt0 * v0.x + wt1 * v1.x;
        acc.y += wt0 * v0.y + wt1 * v1.y;
    }
    if (i < end) {
        int s0 = csr[i];
        float wt0 = __expf(lrelu(als[s0] + aldv) - Mg);
        float2 v0 = *(const float2*)(h + (size_t)s0 * 64 + lane * 2);
        ssum += wt0;
        acc.x += wt0 * v0.x;
        acc.y += wt0 * v0.y;
    }

    float inv = 1.f / (ssum + EPSV);
    *(float2*)(out + (size_t)node * 64 + lane * 2) =
        make_float2(acc.x * inv, acc.y * inv);
}

// ----------------------------------------------------------------------------
// Pool + final
// ----------------------------------------------------------------------------
__global__ void zero_f4(float4* __restrict__ p, int n4) {
    int i = blockIdx.x * blockDim.x + threadIdx.x;
    int stride = gridDim.x * blockDim.x;
    float4 z = make_float4(0.f, 0.f, 0.f, 0.f);
    for (; i < n4; i += stride) p[i] = z;
}

__global__ void counts_k(const int* __restrict__ batch, float* __restrict__ cnt) {
    int g = threadIdx.x;
    if (g >= NGRAPH) return;
    int lo = 0, hi = NN;
    while (lo < hi) { int mid = (lo + hi) >> 1; if (batch[mid] < g) lo = mid + 1; else hi = mid; }
    int a = lo;
    lo = 0; hi = NN;
    while (lo < hi) { int mid = (lo + hi) >> 1; if (batch[mid] < g + 1) lo = mid + 1; else hi = mid; }
    cnt[g] = (float)(lo - a);
}

__global__ void pool_sum(const float* __restrict__ h, const int* __restrict__ batch,
                         float* __restrict__ pool) {
    int c = threadIdx.x & 63;
    int r = threadIdx.x >> 6;
    int start = blockIdx.x * 1024;
    int end = start + 1024;
    if (end > NN) end = NN;
    int cur = -1;
    float acc = 0.f;
    for (int nd = start + r; nd < end; nd += 4) {
        int g = batch[nd];
        if (g != cur) {
            if (cur >= 0) atomicAdd(&pool[cur * 64 + c], acc);
            cur = g;
            acc = 0.f;
        }
        acc += h[(size_t)nd * 64 + c];
    }
    if (cur >= 0) atomicAdd(&pool[cur * 64 + c], acc);
}

__global__ void final_k(const float* __restrict__ pool, const float* __restrict__ cnt,
                        const float* __restrict__ b3,
                        const float* __restrict__ linW, const float* __restrict__ linb,
                        float* __restrict__ out) {
    int g = blockIdx.x;
    int j = threadIdx.x;
    __shared__ float mean[64];
    float cc = fmaxf(cnt[g], 1.f);
    mean[j] = pool[g * 64 + j] / cc + b3[j];
    __syncthreads();
    float acc = 0.f;
#pragma unroll
    for (int k = 0; k < 64; k++) acc += mean[k] * linW[k * 64 + j];
    out[g * 64 + j] = acc + linb[j];
}

// ----------------------------------------------------------------------------
// Host launcher (layer-1 GEMM kept at the profiled stream slot)
// ----------------------------------------------------------------------------
extern "C" void kernel_launch(void* const* d_in, const int* in_sizes, int n_in,
                              void* d_out, int out_size) {
    const float* x     = (const float*)d_in[0];
    const void*  ei    = d_in[1];
    const void*  batch = d_in[3];
    const float* W1  = (const float*)d_in[4];
    const float* a1s = (const float*)d_in[5];
    const float* a1d = (const float*)d_in[6];
    const float* b1  = (const float*)d_in[7];
    const float* W2  = (const float*)d_in[8];
    const float* a2s = (const float*)d_in[9];
    const float* a2d = (const float*)d_in[10];
    const float* b2  = (const float*)d_in[11];
    const float* W3  = (const float*)d_in[12];
    const float* a3s = (const float*)d_in[13];
    const float* a3d = (const float*)d_in[14];
    const float* b3  = (const float*)d_in[15];
    const float* lW  = (const float*)d_in[16];
    const float* lb  = (const float*)d_in[17];
    float* out = (float*)d_out;

    float *p_h, *p_agg, *p_als, *p_ald, *p_pool, *p_cnt;
    int *p_src, *p_dst, *p_off, *p_cur, *p_csr, *p_batch;
    cudaGetSymbolAddress((void**)&p_h,    g_h);
    cudaGetSymbolAddress((void**)&p_agg,  g_agg);
    cudaGetSymbolAddress((void**)&p_als,  g_als);
    cudaGetSymbolAddress((void**)&p_ald,  g_ald);
    cudaGetSymbolAddress((void**)&p_src,  g_src);
    cudaGetSymbolAddress((void**)&p_dst,  g_dst);
    cudaGetSymbolAddress((void**)&p_off,  g_off);
    cudaGetSymbolAddress((void**)&p_cur,  g_cur);
    cudaGetSymbolAddress((void**)&p_csr,  g_csr);
    cudaGetSymbolAddress((void**)&p_batch,g_batch);
    cudaGetSymbolAddress((void**)&p_pool, g_pool);
    cudaGetSymbolAddress((void**)&p_cnt,  g_cnt);

    const int TB = 256;
    const int mTiles = (NN + 127) / 128;
    const int nodeWarpBlocks = (NN * 32 + TB - 1) / TB;

    detect_dtype<<<1, 32>>>((const unsigned int*)ei);                        // 0
    zero_i<<<(NN + 1 + TB - 1) / TB, TB>>>(p_off, NN + 1);                   // 1
    conv_edges<<<(NEDGE + TB - 1) / TB, TB>>>(ei, p_src, p_dst, p_off);      // 2

    // pos 3: layer-1 GEMM (profiled slot)
    {
        dim3 grid(mTiles, HC12 / 128);
        mma_gemm_fused<128, 4><<<grid, TB>>>(x, W1, p_h, NN, 128, HC12,
                                             a1s, a1d, p_als, p_ald, 0);     // 3
    }

    scan_k<<<1, 1024>>>(p_off, NN + 1);                                      // 4
    set_cursors<<<(NN + TB - 1) / TB, TB>>>(p_off, p_cur);                   // 5
    scatter_csr<<<(NEDGE + TB - 1) / TB, TB>>>(p_src, p_dst, p_cur, p_csr);  // 6
    conv_batch<<<(NN + TB - 1) / TB, TB>>>(batch, p_batch);                  // 7

    // ================= Layer 1 aggregation =================
    gat_agg4<<<nodeWarpBlocks, TB>>>(p_off, p_csr, p_h, p_als, p_ald,
                                     (const float4*)b1, p_agg, 0);

    // ================= Layer 2 =================
    {
        dim3 grid(mTiles, HC12 / 128);
        mma_gemm_fused<128, 4><<<grid, TB>>>(p_agg, W2, p_h, NN, HC12, HC12,
                                             a2s, a2d, p_als, p_ald, 1);
        gat_agg4<<<nodeWarpBlocks, TB>>>(p_off, p_csr, p_h, p_als, p_ald,
                                         (const float4*)b2, p_agg, 1);
    }

    // ================= Layer 3 =================
    {
        dim3 grid(mTiles, 1);
        mma_gemm_fused<64, 1><<<grid, TB>>>(p_agg, W3, p_h, NN, HC12, HC3,
                                            a3s, a3d, p_als, p_ald, 2);
        gat_agg1<<<nodeWarpBlocks, TB>>>(p_off, p_csr, p_h, p_als, p_ald, p_agg, 2);
    }

    // ================= Pool + final linear =================
    zero_f4<<<4, 64>>>((float4*)p_pool, NGRAPH * HC3 / 4);
    counts_k<<<1, 64>>>(p_batch, p_cnt);
    pool_sum<<<(NN + 1023) / 1024, 256>>>(p_agg, p_batch, p_pool);
    final_k<<<NGRAPH, 64>>>(p_pool, p_cnt, b3, lW, lb, out);
}

// round 14
// speedup vs baseline: 1.1802x; 1.1763x over previous
#include <cuda_runtime.h>
#include <cuda_bf16.h>
#include <math.h>
#include <stdint.h>

// ----------------------------------------------------------------------------
// Problem constants
// ----------------------------------------------------------------------------
#define NN      50000
#define EE      800000
#define NEDGE   (EE + NN)       // with self loops = 850000
#define NGRAPH  64
#define HC12    256
#define HC3     64
#define NEG_SLOPE 0.2f
#define EPSV    1e-16f

// ----------------------------------------------------------------------------
// Device scratch
// ----------------------------------------------------------------------------
__device__ __align__(256) float g_h   [(size_t)NN * HC12];
__device__ __align__(256) float g_agg [(size_t)NN * HC12];
__device__ __align__(256) float g_als [NN * 4];
__device__ __align__(256) float g_ald [NN * 4];
__device__ __align__(256) int   g_src [NEDGE];
__device__ __align__(256) int   g_dst [NEDGE];
__device__ __align__(256) int   g_off [NN + 1];
__device__ __align__(256) int   g_cur [NN];
__device__ __align__(256) int   g_csr [NEDGE];
__device__ __align__(256) int   g_batch[NN];
__device__ __align__(256) float g_pool[NGRAPH * HC3];
__device__ __align__(256) float g_cnt [NGRAPH];
__device__ float g_maxv[6];     // (maxs, maxd) per layer
__device__ int   g_is64;

// ----------------------------------------------------------------------------
// Helpers
// ----------------------------------------------------------------------------
__device__ __forceinline__ float lrelu(float x) {
    return x >= 0.f ? x : NEG_SLOPE * x;
}
__device__ __forceinline__ void atomicMaxF(float* addr, float v) {
    if (v >= 0.f) atomicMax((int*)addr, __float_as_int(v));
    else          atomicMin((unsigned int*)addr, __float_as_uint(v));
}

// tf32 split: x -> hi (rna-rounded tf32) and lo (residual as tf32)
__device__ __forceinline__ void split_tf32(float x, uint32_t* hp, uint32_t* lp) {
    uint32_t h;
    asm("cvt.rna.tf32.f32 %0, %1;" : "=r"(h) : "f"(x));
    float r = x - __uint_as_float(h);
    uint32_t l;
    asm("cvt.rna.tf32.f32 %0, %1;" : "=r"(l) : "f"(r));
    *hp = h;
    *lp = l;
}

__device__ __forceinline__ uint32_t to_tf32(float x) {
    uint32_t h;
    asm("cvt.rna.tf32.f32 %0, %1;" : "=r"(h) : "f"(x));
    return h;
}

__device__ __forceinline__ void mma_tf32(float* c, const uint32_t* a,
                                         uint32_t b0, uint32_t b1) {
    asm volatile(
        "mma.sync.aligned.m16n8k8.row.col.f32.tf32.tf32.f32 "
        "{%0,%1,%2,%3}, {%4,%5,%6,%7}, {%8,%9}, {%0,%1,%2,%3};"
        : "+f"(c[0]), "+f"(c[1]), "+f"(c[2]), "+f"(c[3])
        : "r"(a[0]), "r"(a[1]), "r"(a[2]), "r"(a[3]), "r"(b0), "r"(b1));
}

// ----------------------------------------------------------------------------
// Dtype probe + CSR build
// ----------------------------------------------------------------------------
__global__ void detect_dtype(const unsigned int* __restrict__ w) {
    if (threadIdx.x == 0 && blockIdx.x == 0) {
        int all0 = 1;
        for (int i = 1; i < 128; i += 2)
            if (w[i] != 0u) { all0 = 0; break; }
        g_is64 = all0;
    }
    if (blockIdx.x == 0 && threadIdx.x < 6)
        g_maxv[threadIdx.x] = -INFINITY;
}

__global__ void zero_i(int* __restrict__ p, int n) {
    int i = blockIdx.x * blockDim.x + threadIdx.x;
    if (i < n) p[i] = 0;
}

__global__ void conv_edges(const void* __restrict__ ei_raw,
                           int* __restrict__ src, int* __restrict__ dst,
                           int* __restrict__ off) {
    int i = blockIdx.x * blockDim.x + threadIdx.x;
    if (i >= NEDGE) return;
    int sv, dv;
    if (i >= EE) {
        sv = dv = i - EE;
    } else if (g_is64) {
        const long long* e = (const long long*)ei_raw;
        sv = (int)e[i];
        dv = (int)e[EE + i];
    } else {
        const int* e = (const int*)ei_raw;
        sv = e[i];
        dv = e[EE + i];
    }
    src[i] = sv;
    dst[i] = dv;
    atomicAdd(&off[dv + 1], 1);
}

__global__ void conv_batch(const void* __restrict__ b_raw, int* __restrict__ bo) {
    int i = blockIdx.x * blockDim.x + threadIdx.x;
    if (i >= NN) return;
    bo[i] = g_is64 ? (int)((const long long*)b_raw)[i] : ((const int*)b_raw)[i];
}

__global__ void scan_k(int* __restrict__ a, int n) {
    __shared__ int warp_sums[32];
    __shared__ int carry_s;
    int tid = threadIdx.x, lane = tid & 31, wid = tid >> 5;
    if (tid == 0) carry_s = 0;
    __syncthreads();
    for (int base = 0; base < n; base += 1024) {
        int idx = base + tid;
        int v = (idx < n) ? a[idx] : 0;
#pragma unroll
        for (int off = 1; off < 32; off <<= 1) {
            int t = __shfl_up_sync(0xffffffffu, v, off);
            if (lane >= off) v += t;
        }
        if (lane == 31) warp_sums[wid] = v;
        __syncthreads();
        if (wid == 0) {
            int w = warp_sums[lane];
#pragma unroll
            for (int off = 1; off < 32; off <<= 1) {
                int t = __shfl_up_sync(0xffffffffu, w, off);
                if (lane >= off) w += t;
            }
            warp_sums[lane] = w;
        }
        __syncthreads();
        int add = (wid > 0 ? warp_sums[wid - 1] : 0) + carry_s;
        if (idx < n) a[idx] = v + add;
        int total = warp_sums[31];
        __syncthreads();
        if (tid == 0) carry_s += total;
        __syncthreads();
    }
}

__global__ void set_cursors(const int* __restrict__ off, int* __restrict__ cur) {
    int i = blockIdx.x * blockDim.x + threadIdx.x;
    if (i < NN) cur[i] = off[i];
}

__global__ void scatter_csr(const int* __restrict__ src, const int* __restrict__ dst,
                            int* __restrict__ cur, int* __restrict__ csr) {
    int i = blockIdx.x * blockDim.x + threadIdx.x;
    if (i >= NEDGE) return;
    int pos = atomicAdd(&cur[dst[i]], 1);
    csr[pos] = src[i];
}

// ----------------------------------------------------------------------------
// 2xTF32 (A split, B plain tf32) tensor-core GEMM, round-10 schedule:
//  - separate As_hi/As_lo arrays, single Bs array, LDS.32 fragment loads
//  - no prefetch (v2/v3's prefetch+uint2 caused alu-pipe regression)
//  - D = Ahi·B + Alo·B : 16 MMAs + 32 LDS per warp/kk-step (was 24 + 48)
//  - error budget: B tf32 rounding only (~1e-4 rel, 10x under 1e-3 threshold)
//  - fused attention-dot epilogue + per-layer global-max side reduction
// ----------------------------------------------------------------------------
template <int BN, int H>
__global__ __launch_bounds__(256, 2)
void mma_gemm_fused(const float* __restrict__ A, const float* __restrict__ B,
                    float* __restrict__ C, int M, int K, int Ncols,
                    const float* __restrict__ a_src, const float* __restrict__ a_dst,
                    float* __restrict__ als, float* __restrict__ ald, int layer) {
    const int BM = 128, BK = 16;
    const int WARPS_N = BN / 64;
    const int WARPS_M = 8 / WARPS_N;
    const int WROWS = BM / WARPS_M;      // 32 or 16
    const int MT = WROWS / 16;           // 2 or 1
    const int AS = BM + 8;
    const int BS = BN + 8;

    __shared__ uint32_t As_hi[BK][AS], As_lo[BK][AS];
    __shared__ uint32_t Bs[BK][BS];
    __shared__ float smax1[8], smax2[8];

    int tid = threadIdx.x;
    int wid = tid >> 5;
    int lane = tid & 31;
    int lm = lane >> 2;
    int lk = lane & 3;

    int warpN = wid % WARPS_N;
    int warpM = wid / WARPS_N;

    int mBlock = blockIdx.x * BM;
    int nBlock = blockIdx.y * BN;

    float c[MT][8][4];
#pragma unroll
    for (int i = 0; i < MT; i++)
#pragma unroll
        for (int j = 0; j < 8; j++)
#pragma unroll
            for (int q = 0; q < 4; q++) c[i][j][q] = 0.f;

    int aRow = tid >> 1;
    int aColB = (tid & 1) * 8;
    int gr = mBlock + aRow;
    bool aAct = (gr < M);

    for (int k0 = 0; k0 < K; k0 += BK) {
        // ---- A tile (split hi/lo) ----
        {
            float4 v0 = make_float4(0.f, 0.f, 0.f, 0.f), v1 = v0;
            if (aAct) {
                const float* ap = A + (size_t)gr * K + k0 + aColB;
                v0 = *(const float4*)ap;
                v1 = *(const float4*)(ap + 4);
            }
            float av[8] = {v0.x, v0.y, v0.z, v0.w, v1.x, v1.y, v1.z, v1.w};
#pragma unroll
            for (int q = 0; q < 8; q++)
                split_tf32(av[q], &As_hi[aColB + q][aRow], &As_lo[aColB + q][aRow]);
        }
        // ---- B tile (plain tf32) ----
        if (BN == 128) {
            int row = tid >> 5;
            int col4 = tid & 31;
#pragma unroll
            for (int rr = 0; rr < 2; rr++) {
                int r = row + rr * 8;
                const float* bp = B + (size_t)(k0 + r) * Ncols + nBlock + col4 * 4;
                float4 v = *(const float4*)bp;
                Bs[r][col4 * 4 + 0] = to_tf32(v.x);
                Bs[r][col4 * 4 + 1] = to_tf32(v.y);
                Bs[r][col4 * 4 + 2] = to_tf32(v.z);
                Bs[r][col4 * 4 + 3] = to_tf32(v.w);
            }
        } else {
            int row = tid >> 4;
            int col4 = tid & 15;
            const float* bp = B + (size_t)(k0 + row) * Ncols + nBlock + col4 * 4;
            float4 v = *(const float4*)bp;
            Bs[row][col4 * 4 + 0] = to_tf32(v.x);
            Bs[row][col4 * 4 + 1] = to_tf32(v.y);
            Bs[row][col4 * 4 + 2] = to_tf32(v.z);
            Bs[row][col4 * 4 + 3] = to_tf32(v.w);
        }
        __syncthreads();

        // ---- compute: hoist A fragments, load B once per j ----
#pragma unroll
        for (int kk = 0; kk < BK; kk += 8) {
            uint32_t ah[MT][4], al[MT][4];
#pragma unroll
            for (int i = 0; i < MT; i++) {
                int m0 = warpM * WROWS + i * 16 + lm;
                ah[i][0] = As_hi[kk + lk][m0];     ah[i][1] = As_hi[kk + lk][m0 + 8];
                ah[i][2] = As_hi[kk + lk + 4][m0]; ah[i][3] = As_hi[kk + lk + 4][m0 + 8];
                al[i][0] = As_lo[kk + lk][m0];     al[i][1] = As_lo[kk + lk][m0 + 8];
                al[i][2] = As_lo[kk + lk + 4][m0]; al[i][3] = As_lo[kk + lk + 4][m0 + 8];
            }
#pragma unroll
            for (int j = 0; j < 8; j++) {
                int n0 = warpN * 64 + j * 8 + lm;
                uint32_t b0 = Bs[kk + lk][n0];
                uint32_t b1 = Bs[kk + lk + 4][n0];
#pragma unroll
                for (int i = 0; i < MT; i++) {
                    mma_tf32(c[i][j], ah[i], b0, b1);
                    mma_tf32(c[i][j], al[i], b0, b1);
                }
            }
        }
        __syncthreads();
    }

    // ---- epilogue: store C + fused attention dots + global-max side band ----
    int head_base = nBlock + warpN * 64;
    int head = head_base >> 6;

    float wm1 = -INFINITY, wm2 = -INFINITY;

#pragma unroll
    for (int i = 0; i < MT; i++) {
        int r0 = mBlock + warpM * WROWS + i * 16 + lm;
        int r1 = r0 + 8;
        float d1a = 0.f, d2a = 0.f, d1b = 0.f, d2b = 0.f;
#pragma unroll
        for (int j = 0; j < 8; j++) {
            int colg = head_base + j * 8 + lk * 2;
            float as0 = a_src[colg], as1 = a_src[colg + 1];
            float ad0 = a_dst[colg], ad1 = a_dst[colg + 1];
            float* cc = c[i][j];
            d1a += cc[0] * as0 + cc[1] * as1;
            d2a += cc[0] * ad0 + cc[1] * ad1;
            d1b += cc[2] * as0 + cc[3] * as1;
            d2b += cc[2] * ad0 + cc[3] * ad1;
            if (r0 < M) *(float2*)&C[(size_t)r0 * Ncols + colg] = make_float2(cc[0], cc[1]);
            if (r1 < M) *(float2*)&C[(size_t)r1 * Ncols + colg] = make_float2(cc[2], cc[3]);
        }
#pragma unroll
        for (int off = 1; off <= 2; off <<= 1) {
            d1a += __shfl_xor_sync(0xffffffffu, d1a, off);
            d2a += __shfl_xor_sync(0xffffffffu, d2a, off);
            d1b += __shfl_xor_sync(0xffffffffu, d1b, off);
            d2b += __shfl_xor_sync(0xffffffffu, d2b, off);
        }
        if (r0 < M) { wm1 = fmaxf(wm1, d1a); wm2 = fmaxf(wm2, d2a); }
        if (r1 < M) { wm1 = fmaxf(wm1, d1b); wm2 = fmaxf(wm2, d2b); }
        if (lk == 0) {
            if (r0 < M) { als[r0 * H + head] = d1a; ald[r0 * H + head] = d2a; }
            if (r1 < M) { als[r1 * H + head] = d1b; ald[r1 * H + head] = d2b; }
        }
    }

#pragma unroll
    for (int off = 16; off > 0; off >>= 1) {
        wm1 = fmaxf(wm1, __shfl_xor_sync(0xffffffffu, wm1, off));
        wm2 = fmaxf(wm2, __shfl_xor_sync(0xffffffffu, wm2, off));
    }
    if (lane == 0) { smax1[wid] = wm1; smax2[wid] = wm2; }
    __syncthreads();
    if (tid == 0) {
        float m1 = smax1[0], m2 = smax2[0];
#pragma unroll
        for (int i = 1; i < 8; i++) {
            m1 = fmaxf(m1, smax1[i]);
            m2 = fmaxf(m2, smax2[i]);
        }
        atomicMaxF(&g_maxv[2 * layer], m1);
        atomicMaxF(&g_maxv[2 * layer + 1], m2);
    }
}

// ----------------------------------------------------------------------------
// CSR gather-aggregate, H=4 C=64. Warp per dst node; global-shift softmax.
// ----------------------------------------------------------------------------
__global__ void gat_agg4(const int* __restrict__ off, const int* __restrict__ csr,
                         const float* __restrict__ h,
                         const float* __restrict__ als, const float* __restrict__ ald,
                         const float4* __restrict__ bias, float* __restrict__ out,
                         int layer) {
    int node = (blockIdx.x * blockDim.x + threadIdx.x) >> 5;
    int lane = threadIdx.x & 31;
    if (node >= NN) return;

    float Mg = fmaxf(0.f, g_maxv[2 * layer] + g_maxv[2 * layer + 1]);
    int head = lane >> 3;
    float aldv = ald[node * 4 + head];

    float4 acc0 = make_float4(0.f, 0.f, 0.f, 0.f);
    float4 acc1 = make_float4(0.f, 0.f, 0.f, 0.f);
    float ssum = 0.f;

    int beg = off[node], end = off[node + 1];
    int i = beg;
    for (; i + 1 < end; i += 2) {
        int s0 = csr[i], s1 = csr[i + 1];
        float wt0 = __expf(lrelu(als[s0 * 4 + head] + aldv) - Mg);
        float wt1 = __expf(lrelu(als[s1 * 4 + head] + aldv) - Mg);
        const float4* h0 = (const float4*)(h + (size_t)s0 * 256 + lane * 8);
        const float4* h1 = (const float4*)(h + (size_t)s1 * 256 + lane * 8);
        float4 v00 = h0[0], v01 = h0[1];
        float4 v10 = h1[0], v11 = h1[1];
        ssum += wt0 + wt1;
        acc0.x += wt0 * v00.x + wt1 * v10.x;
        acc0.y += wt0 * v00.y + wt1 * v10.y;
        acc0.z += wt0 * v00.z + wt1 * v10.z;
        acc0.w += wt0 * v00.w + wt1 * v10.w;
        acc1.x += wt0 * v01.x + wt1 * v11.x;
        acc1.y += wt0 * v01.y + wt1 * v11.y;
        acc1.z += wt0 * v01.z + wt1 * v11.z;
        acc1.w += wt0 * v01.w + wt1 * v11.w;
    }
    if (i < end) {
        int s0 = csr[i];
        float wt0 = __expf(lrelu(als[s0 * 4 + head] + aldv) - Mg);
        const float4* h0 = (const float4*)(h + (size_t)s0 * 256 + lane * 8);
        float4 v00 = h0[0], v01 = h0[1];
        ssum += wt0;
        acc0.x += wt0 * v00.x; acc0.y += wt0 * v00.y;
        acc0.z += wt0 * v00.z; acc0.w += wt0 * v00.w;
        acc1.x += wt0 * v01.x; acc1.y += wt0 * v01.y;
        acc1.z += wt0 * v01.z; acc1.w += wt0 * v01.w;
    }

    float inv = 1.f / (ssum + EPSV);
    float4 b0 = bias[lane * 2];
    float4 b1 = bias[lane * 2 + 1];
    float4 r0, r1;
    r0.x = fmaxf(acc0.x * inv + b0.x, 0.f);
    r0.y = fmaxf(acc0.y * inv + b0.y, 0.f);
    r0.z = fmaxf(acc0.z * inv + b0.z, 0.f);
    r0.w = fmaxf(acc0.w * inv + b0.w, 0.f);
    r1.x = fmaxf(acc1.x * inv + b1.x, 0.f);
    r1.y = fmaxf(acc1.y * inv + b1.y, 0.f);
    r1.z = fmaxf(acc1.z * inv + b1.z, 0.f);
    r1.w = fmaxf(acc1.w * inv + b1.w, 0.f);
    float4* op = (float4*)(out + (size_t)node * 256 + lane * 8);
    op[0] = r0;
    op[1] = r1;
}

// CSR gather-aggregate, H=1 C=64 (unroll-2)
__global__ void gat_agg1(const int* __restrict__ off, const int* __restrict__ csr,
                         const float* __restrict__ h,
                         const float* __restrict__ als, const float* __restrict__ ald,
                         float* __restrict__ out, int layer) {
    int node = (blockIdx.x * blockDim.x + threadIdx.x) >> 5;
    int lane = threadIdx.x & 31;
    if (node >= NN) return;

    float Mg = fmaxf(0.f, g_maxv[2 * layer] + g_maxv[2 * layer + 1]);
    float aldv = ald[node];

    float2 acc = make_float2(0.f, 0.f);
    float ssum = 0.f;

    int beg = off[node], end = off[node + 1];
    int i = beg;
    for (; i + 1 < end; i += 2) {
        int s0 = csr[i], s1 = csr[i + 1];
        float wt0 = __expf(lrelu(als[s0] + aldv) - Mg);
        float wt1 = __expf(lrelu(als[s1] + aldv) - Mg);
        float2 v0 = *(const float2*)(h + (size_t)s0 * 64 + lane * 2);
        float2 v1 = *(const float2*)(h + (size_t)s1 * 64 + lane * 2);
        ssum += wt0 + wt1;
        acc.x += wt0 * v0.x + wt1 * v1.x;
        acc.y += wt0 * v0.y + wt1 * v1.y;
    }
    if (i < end) {
        int s0 = csr[i];
        float wt0 = __expf(lrelu(als[s0] + aldv) - Mg);
        float2 v0 = *(const float2*)(h + (size_t)s0 * 64 + lane * 2);
        ssum += wt0;
        acc.x += wt0 * v0.x;
        acc.y += wt0 * v0.y;
    }

    float inv = 1.f / (ssum + EPSV);
    *(float2*)(out + (size_t)node * 64 + lane * 2) =
        make_float2(acc.x * inv, acc.y * inv);
}

// ----------------------------------------------------------------------------
// Pool + final
// ----------------------------------------------------------------------------
__global__ void zero_f4(float4* __restrict__ p, int n4) {
    int i = blockIdx.x * blockDim.x + threadIdx.x;
    int stride = gridDim.x * blockDim.x;
    float4 z = make_float4(0.f, 0.f, 0.f, 0.f);
    for (; i < n4; i += stride) p[i] = z;
}

__global__ void counts_k(const int* __restrict__ batch, float* __restrict__ cnt) {
    int g = threadIdx.x;
    if (g >= NGRAPH) return;
    int lo = 0, hi = NN;
    while (lo < hi) { int mid = (lo + hi) >> 1; if (batch[mid] < g) lo = mid + 1; else hi = mid; }
    int a = lo;
    lo = 0; hi = NN;
    while (lo < hi) { int mid = (lo + hi) >> 1; if (batch[mid] < g + 1) lo = mid + 1; else hi = mid; }
    cnt[g] = (float)(lo - a);
}

__global__ void pool_sum(const float* __restrict__ h, const int* __restrict__ batch,
                         float* __restrict__ pool) {
    int c = threadIdx.x & 63;
    int r = threadIdx.x >> 6;
    int start = blockIdx.x * 1024;
    int end = start + 1024;
    if (end > NN) end = NN;
    int cur = -1;
    float acc = 0.f;
    for (int nd = start + r; nd < end; nd += 4) {
        int g = batch[nd];
        if (g != cur) {
            if (cur >= 0) atomicAdd(&pool[cur * 64 + c], acc);
            cur = g;
            acc = 0.f;
        }
        acc += h[(size_t)nd * 64 + c];
    }
    if (cur >= 0) atomicAdd(&pool[cur * 64 + c], acc);
}

__global__ void final_k(const float* __restrict__ pool, const float* __restrict__ cnt,
                        const float* __restrict__ b3,
                        const float* __restrict__ linW, const float* __restrict__ linb,
                        float* __restrict__ out) {
    int g = blockIdx.x;
    int j = threadIdx.x;
    __shared__ float mean[64];
    float cc = fmaxf(cnt[g], 1.f);
    mean[j] = pool[g * 64 + j] / cc + b3[j];
    __syncthreads();
    float acc = 0.f;
#pragma unroll
    for (int k = 0; k < 64; k++) acc += mean[k] * linW[k * 64 + j];
    out[g * 64 + j] = acc + linb[j];
}

// ----------------------------------------------------------------------------
// Host launcher (layer-1 GEMM kept at the profiled stream slot)
// ----------------------------------------------------------------------------
extern "C" void kernel_launch(void* const* d_in, const int* in_sizes, int n_in,
                              void* d_out, int out_size) {
    const float* x     = (const float*)d_in[0];
    const void*  ei    = d_in[1];
    const void*  batch = d_in[3];
    const float* W1  = (const float*)d_in[4];
    const float* a1s = (const float*)d_in[5];
    const float* a1d = (const float*)d_in[6];
    const float* b1  = (const float*)d_in[7];
    const float* W2  = (const float*)d_in[8];
    const float* a2s = (const float*)d_in[9];
    const float* a2d = (const float*)d_in[10];
    const float* b2  = (const float*)d_in[11];
    const float* W3  = (const float*)d_in[12];
    const float* a3s = (const float*)d_in[13];
    const float* a3d = (const float*)d_in[14];
    const float* b3  = (const float*)d_in[15];
    const float* lW  = (const float*)d_in[16];
    const float* lb  = (const float*)d_in[17];
    float* out = (float*)d_out;

    float *p_h, *p_agg, *p_als, *p_ald, *p_pool, *p_cnt;
    int *p_src, *p_dst, *p_off, *p_cur, *p_csr, *p_batch;
    cudaGetSymbolAddress((void**)&p_h,    g_h);
    cudaGetSymbolAddress((void**)&p_agg,  g_agg);
    cudaGetSymbolAddress((void**)&p_als,  g_als);
    cudaGetSymbolAddress((void**)&p_ald,  g_ald);
    cudaGetSymbolAddress((void**)&p_src,  g_src);
    cudaGetSymbolAddress((void**)&p_dst,  g_dst);
    cudaGetSymbolAddress((void**)&p_off,  g_off);
    cudaGetSymbolAddress((void**)&p_cur,  g_cur);
    cudaGetSymbolAddress((void**)&p_csr,  g_csr);
    cudaGetSymbolAddress((void**)&p_batch,g_batch);
    cudaGetSymbolAddress((void**)&p_pool, g_pool);
    cudaGetSymbolAddress((void**)&p_cnt,  g_cnt);

    const int TB = 256;
    const int mTiles = (NN + 127) / 128;
    const int nodeWarpBlocks = (NN * 32 + TB - 1) / TB;

    detect_dtype<<<1, 32>>>((const unsigned int*)ei);                        // 0
    zero_i<<<(NN + 1 + TB - 1) / TB, TB>>>(p_off, NN + 1);                   // 1
    conv_edges<<<(NEDGE + TB - 1) / TB, TB>>>(ei, p_src, p_dst, p_off);      // 2

    // pos 3: layer-1 GEMM (profiled slot)
    {
        dim3 grid(mTiles, HC12 / 128);
        mma_gemm_fused<128, 4><<<grid, TB>>>(x, W1, p_h, NN, 128, HC12,
                                             a1s, a1d, p_als, p_ald, 0);     // 3
    }

    scan_k<<<1, 1024>>>(p_off, NN + 1);                                      // 4
    set_cursors<<<(NN + TB - 1) / TB, TB>>>(p_off, p_cur);                   // 5
    scatter_csr<<<(NEDGE + TB - 1) / TB, TB>>>(p_src, p_dst, p_cur, p_csr);  // 6
    conv_batch<<<(NN + TB - 1) / TB, TB>>>(batch, p_batch);                  // 7

    // ================= Layer 1 aggregation =================
    gat_agg4<<<nodeWarpBlocks, TB>>>(p_off, p_csr, p_h, p_als, p_ald,
                                     (const float4*)b1, p_agg, 0);

    // ================= Layer 2 =================
    {
        dim3 grid(mTiles, HC12 / 128);
        mma_gemm_fused<128, 4><<<grid, TB>>>(p_agg, W2, p_h, NN, HC12, HC12,
                                             a2s, a2d, p_als, p_ald, 1);
        gat_agg4<<<nodeWarpBlocks, TB>>>(p_off, p_csr, p_h, p_als, p_ald,
                                         (const float4*)b2, p_agg, 1);
    }

    // ================= Layer 3 =================
    {
        dim3 grid(mTiles, 1);
        mma_gemm_fused<64, 1><<<grid, TB>>>(p_agg, W3, p_h, NN, HC12, HC3,
                                            a3s, a3d, p_als, p_ald, 2);
        gat_agg1<<<nodeWarpBlocks, TB>>>(p_off, p_csr, p_h, p_als, p_ald, p_agg, 2);
    }

    // ================= Pool + final linear =================
    zero_f4<<<4, 64>>>((float4*)p_pool, NGRAPH * HC3 / 4);
    counts_k<<<1, 64>>>(p_batch, p_cnt);
    pool_sum<<<(NN + 1023) / 1024, 256>>>(p_agg, p_batch, p_pool);
    final_k<<<NGRAPH, 64>>>(p_pool, p_cnt, b3, lW, lb, out);
}

// round 15
// speedup vs baseline: 1.3344x; 1.1307x over previous
#include <cuda_runtime.h>
#include <cuda_bf16.h>
#include <math.h>
#include <stdint.h>

// ----------------------------------------------------------------------------
// Problem constants
// ----------------------------------------------------------------------------
#define NN      50000
#define EE      800000
#define NEDGE   (EE + NN)       // with self loops = 850000
#define NGRAPH  64
#define HC12    256
#define HC3     64
#define NEG_SLOPE 0.2f
#define EPSV    1e-16f

// ----------------------------------------------------------------------------
// Device scratch
// ----------------------------------------------------------------------------
__device__ __align__(256) float g_h   [(size_t)NN * HC12];
__device__ __align__(256) float g_agg [(size_t)NN * HC12];
__device__ __align__(256) float g_als [NN * 4];
__device__ __align__(256) float g_ald [NN * 4];
__device__ __align__(256) int   g_src [NEDGE];
__device__ __align__(256) int   g_dst [NEDGE];
__device__ __align__(256) int   g_off [NN + 1];
__device__ __align__(256) int   g_cur [NN];
__device__ __align__(256) int   g_csr [NEDGE];
__device__ __align__(256) int   g_batch[NN];
__device__ __align__(256) float g_pool[NGRAPH * HC3];
__device__ __align__(256) float g_cnt [NGRAPH];
__device__ float g_maxv[6];     // (maxs, maxd) per layer
__device__ int   g_is64;

// ----------------------------------------------------------------------------
// Helpers
// ----------------------------------------------------------------------------
__device__ __forceinline__ float lrelu(float x) {
    return x >= 0.f ? x : NEG_SLOPE * x;
}
__device__ __forceinline__ void atomicMaxF(float* addr, float v) {
    if (v >= 0.f) atomicMax((int*)addr, __float_as_int(v));
    else          atomicMin((unsigned int*)addr, __float_as_uint(v));
}

__device__ __forceinline__ uint32_t to_tf32(float x) {
    uint32_t h;
    asm("cvt.rna.tf32.f32 %0, %1;" : "=r"(h) : "f"(x));
    return h;
}

__device__ __forceinline__ void mma_tf32(float* c, const uint32_t* a,
                                         uint32_t b0, uint32_t b1) {
    asm volatile(
        "mma.sync.aligned.m16n8k8.row.col.f32.tf32.tf32.f32 "
        "{%0,%1,%2,%3}, {%4,%5,%6,%7}, {%8,%9}, {%0,%1,%2,%3};"
        : "+f"(c[0]), "+f"(c[1]), "+f"(c[2]), "+f"(c[3])
        : "r"(a[0]), "r"(a[1]), "r"(a[2]), "r"(a[3]), "r"(b0), "r"(b1));
}

// ----------------------------------------------------------------------------
// Dtype probe + CSR build
// ----------------------------------------------------------------------------
__global__ void detect_dtype(const unsigned int* __restrict__ w) {
    if (threadIdx.x == 0 && blockIdx.x == 0) {
        int all0 = 1;
        for (int i = 1; i < 128; i += 2)
            if (w[i] != 0u) { all0 = 0; break; }
        g_is64 = all0;
    }
    if (blockIdx.x == 0 && threadIdx.x < 6)
        g_maxv[threadIdx.x] = -INFINITY;
}

__global__ void zero_i(int* __restrict__ p, int n) {
    int i = blockIdx.x * blockDim.x + threadIdx.x;
    if (i < n) p[i] = 0;
}

__global__ void conv_edges(const void* __restrict__ ei_raw,
                           int* __restrict__ src, int* __restrict__ dst,
                           int* __restrict__ off) {
    int i = blockIdx.x * blockDim.x + threadIdx.x;
    if (i >= NEDGE) return;
    int sv, dv;
    if (i >= EE) {
        sv = dv = i - EE;
    } else if (g_is64) {
        const long long* e = (const long long*)ei_raw;
        sv = (int)e[i];
        dv = (int)e[EE + i];
    } else {
        const int* e = (const int*)ei_raw;
        sv = e[i];
        dv = e[EE + i];
    }
    src[i] = sv;
    dst[i] = dv;
    atomicAdd(&off[dv + 1], 1);
}

__global__ void conv_batch(const void* __restrict__ b_raw, int* __restrict__ bo) {
    int i = blockIdx.x * blockDim.x + threadIdx.x;
    if (i >= NN) return;
    bo[i] = g_is64 ? (int)((const long long*)b_raw)[i] : ((const int*)b_raw)[i];
}

__global__ void scan_k(int* __restrict__ a, int n) {
    __shared__ int warp_sums[32];
    __shared__ int carry_s;
    int tid = threadIdx.x, lane = tid & 31, wid = tid >> 5;
    if (tid == 0) carry_s = 0;
    __syncthreads();
    for (int base = 0; base < n; base += 1024) {
        int idx = base + tid;
        int v = (idx < n) ? a[idx] : 0;
#pragma unroll
        for (int off = 1; off < 32; off <<= 1) {
            int t = __shfl_up_sync(0xffffffffu, v, off);
            if (lane >= off) v += t;
        }
        if (lane == 31) warp_sums[wid] = v;
        __syncthreads();
        if (wid == 0) {
            int w = warp_sums[lane];
#pragma unroll
            for (int off = 1; off < 32; off <<= 1) {
                int t = __shfl_up_sync(0xffffffffu, w, off);
                if (lane >= off) w += t;
            }
            warp_sums[lane] = w;
        }
        __syncthreads();
        int add = (wid > 0 ? warp_sums[wid - 1] : 0) + carry_s;
        if (idx < n) a[idx] = v + add;
        int total = warp_sums[31];
        __syncthreads();
        if (tid == 0) carry_s += total;
        __syncthreads();
    }
}

__global__ void set_cursors(const int* __restrict__ off, int* __restrict__ cur) {
    int i = blockIdx.x * blockDim.x + threadIdx.x;
    if (i < NN) cur[i] = off[i];
}

__global__ void scatter_csr(const int* __restrict__ src, const int* __restrict__ dst,
                            int* __restrict__ cur, int* __restrict__ csr) {
    int i = blockIdx.x * blockDim.x + threadIdx.x;
    if (i >= NEDGE) return;
    int pos = atomicAdd(&cur[dst[i]], 1);
    csr[pos] = src[i];
}

// ----------------------------------------------------------------------------
// Plain TF32 tensor-core GEMM (round-10 schedule):
//  - single As / Bs arrays (tf32), LDS.32 fragment loads
//  - 8 MMAs + 24 LDS per warp/kk-step (was 16 + 32 in 2xtf32)
//  - error budget: A+B tf32 rounding ~4e-4 end-to-end (2.5x under 1e-3)
//  - fused attention-dot epilogue + per-layer global-max side reduction
// ----------------------------------------------------------------------------
template <int BN, int H>
__global__ __launch_bounds__(256, 2)
void mma_gemm_fused(const float* __restrict__ A, const float* __restrict__ B,
                    float* __restrict__ C, int M, int K, int Ncols,
                    const float* __restrict__ a_src, const float* __restrict__ a_dst,
                    float* __restrict__ als, float* __restrict__ ald, int layer) {
    const int BM = 128, BK = 16;
    const int WARPS_N = BN / 64;
    const int WARPS_M = 8 / WARPS_N;
    const int WROWS = BM / WARPS_M;      // 32 or 16
    const int MT = WROWS / 16;           // 2 or 1
    const int AS = BM + 8;
    const int BS = BN + 8;

    __shared__ uint32_t As[BK][AS];
    __shared__ uint32_t Bs[BK][BS];
    __shared__ float smax1[8], smax2[8];

    int tid = threadIdx.x;
    int wid = tid >> 5;
    int lane = tid & 31;
    int lm = lane >> 2;
    int lk = lane & 3;

    int warpN = wid % WARPS_N;
    int warpM = wid / WARPS_N;

    int mBlock = blockIdx.x * BM;
    int nBlock = blockIdx.y * BN;

    float c[MT][8][4];
#pragma unroll
    for (int i = 0; i < MT; i++)
#pragma unroll
        for (int j = 0; j < 8; j++)
#pragma unroll
            for (int q = 0; q < 4; q++) c[i][j][q] = 0.f;

    int aRow = tid >> 1;
    int aColB = (tid & 1) * 8;
    int gr = mBlock + aRow;
    bool aAct = (gr < M);

    for (int k0 = 0; k0 < K; k0 += BK) {
        // ---- A tile (tf32) ----
        {
            float4 v0 = make_float4(0.f, 0.f, 0.f, 0.f), v1 = v0;
            if (aAct) {
                const float* ap = A + (size_t)gr * K + k0 + aColB;
                v0 = *(const float4*)ap;
                v1 = *(const float4*)(ap + 4);
            }
            float av[8] = {v0.x, v0.y, v0.z, v0.w, v1.x, v1.y, v1.z, v1.w};
#pragma unroll
            for (int q = 0; q < 8; q++)
                As[aColB + q][aRow] = to_tf32(av[q]);
        }
        // ---- B tile (tf32) ----
        if (BN == 128) {
            int row = tid >> 5;
            int col4 = tid & 31;
#pragma unroll
            for (int rr = 0; rr < 2; rr++) {
                int r = row + rr * 8;
                const float* bp = B + (size_t)(k0 + r) * Ncols + nBlock + col4 * 4;
                float4 v = *(const float4*)bp;
                Bs[r][col4 * 4 + 0] = to_tf32(v.x);
                Bs[r][col4 * 4 + 1] = to_tf32(v.y);
                Bs[r][col4 * 4 + 2] = to_tf32(v.z);
                Bs[r][col4 * 4 + 3] = to_tf32(v.w);
            }
        } else {
            int row = tid >> 4;
            int col4 = tid & 15;
            const float* bp = B + (size_t)(k0 + row) * Ncols + nBlock + col4 * 4;
            float4 v = *(const float4*)bp;
            Bs[row][col4 * 4 + 0] = to_tf32(v.x);
            Bs[row][col4 * 4 + 1] = to_tf32(v.y);
            Bs[row][col4 * 4 + 2] = to_tf32(v.z);
            Bs[row][col4 * 4 + 3] = to_tf32(v.w);
        }
        __syncthreads();

        // ---- compute: hoist A fragments, load B once per j ----
#pragma unroll
        for (int kk = 0; kk < BK; kk += 8) {
            uint32_t ah[MT][4];
#pragma unroll
            for (int i = 0; i < MT; i++) {
                int m0 = warpM * WROWS + i * 16 + lm;
                ah[i][0] = As[kk + lk][m0];     ah[i][1] = As[kk + lk][m0 + 8];
                ah[i][2] = As[kk + lk + 4][m0]; ah[i][3] = As[kk + lk + 4][m0 + 8];
            }
#pragma unroll
            for (int j = 0; j < 8; j++) {
                int n0 = warpN * 64 + j * 8 + lm;
                uint32_t b0 = Bs[kk + lk][n0];
                uint32_t b1 = Bs[kk + lk + 4][n0];
#pragma unroll
                for (int i = 0; i < MT; i++)
                    mma_tf32(c[i][j], ah[i], b0, b1);
            }
        }
        __syncthreads();
    }

    // ---- epilogue: store C + fused attention dots + global-max side band ----
    int head_base = nBlock + warpN * 64;
    int head = head_base >> 6;

    float wm1 = -INFINITY, wm2 = -INFINITY;

#pragma unroll
    for (int i = 0; i < MT; i++) {
        int r0 = mBlock + warpM * WROWS + i * 16 + lm;
        int r1 = r0 + 8;
        float d1a = 0.f, d2a = 0.f, d1b = 0.f, d2b = 0.f;
#pragma unroll
        for (int j = 0; j < 8; j++) {
            int colg = head_base + j * 8 + lk * 2;
            float as0 = a_src[colg], as1 = a_src[colg + 1];
            float ad0 = a_dst[colg], ad1 = a_dst[colg + 1];
            float* cc = c[i][j];
            d1a += cc[0] * as0 + cc[1] * as1;
            d2a += cc[0] * ad0 + cc[1] * ad1;
            d1b += cc[2] * as0 + cc[3] * as1;
            d2b += cc[2] * ad0 + cc[3] * ad1;
            if (r0 < M) *(float2*)&C[(size_t)r0 * Ncols + colg] = make_float2(cc[0], cc[1]);
            if (r1 < M) *(float2*)&C[(size_t)r1 * Ncols + colg] = make_float2(cc[2], cc[3]);
        }
#pragma unroll
        for (int off = 1; off <= 2; off <<= 1) {
            d1a += __shfl_xor_sync(0xffffffffu, d1a, off);
            d2a += __shfl_xor_sync(0xffffffffu, d2a, off);
            d1b += __shfl_xor_sync(0xffffffffu, d1b, off);
            d2b += __shfl_xor_sync(0xffffffffu, d2b, off);
        }
        if (r0 < M) { wm1 = fmaxf(wm1, d1a); wm2 = fmaxf(wm2, d2a); }
        if (r1 < M) { wm1 = fmaxf(wm1, d1b); wm2 = fmaxf(wm2, d2b); }
        if (lk == 0) {
            if (r0 < M) { als[r0 * H + head] = d1a; ald[r0 * H + head] = d2a; }
            if (r1 < M) { als[r1 * H + head] = d1b; ald[r1 * H + head] = d2b; }
        }
    }

#pragma unroll
    for (int off = 16; off > 0; off >>= 1) {
        wm1 = fmaxf(wm1, __shfl_xor_sync(0xffffffffu, wm1, off));
        wm2 = fmaxf(wm2, __shfl_xor_sync(0xffffffffu, wm2, off));
    }
    if (lane == 0) { smax1[wid] = wm1; smax2[wid] = wm2; }
    __syncthreads();
    if (tid == 0) {
        float m1 = smax1[0], m2 = smax2[0];
#pragma unroll
        for (int i = 1; i < 8; i++) {
            m1 = fmaxf(m1, smax1[i]);
            m2 = fmaxf(m2, smax2[i]);
        }
        atomicMaxF(&g_maxv[2 * layer], m1);
        atomicMaxF(&g_maxv[2 * layer + 1], m2);
    }
}

// ----------------------------------------------------------------------------
// CSR gather-aggregate, H=4 C=64. Warp per dst node; global-shift softmax.
// ----------------------------------------------------------------------------
__global__ void gat_agg4(const int* __restrict__ off, const int* __restrict__ csr,
                         const float* __restrict__ h,
                         const float* __restrict__ als, const float* __restrict__ ald,
                         const float4* __restrict__ bias, float* __restrict__ out,
                         int layer) {
    int node = (blockIdx.x * blockDim.x + threadIdx.x) >> 5;
    int lane = threadIdx.x & 31;
    if (node >= NN) return;

    float Mg = fmaxf(0.f, g_maxv[2 * layer] + g_maxv[2 * layer + 1]);
    int head = lane >> 3;
    float aldv = ald[node * 4 + head];

    float4 acc0 = make_float4(0.f, 0.f, 0.f, 0.f);
    float4 acc1 = make_float4(0.f, 0.f, 0.f, 0.f);
    float ssum = 0.f;

    int beg = off[node], end = off[node + 1];
    int i = beg;
    for (; i + 1 < end; i += 2) {
        int s0 = csr[i], s1 = csr[i + 1];
        float wt0 = __expf(lrelu(als[s0 * 4 + head] + aldv) - Mg);
        float wt1 = __expf(lrelu(als[s1 * 4 + head] + aldv) - Mg);
        const float4* h0 = (const float4*)(h + (size_t)s0 * 256 + lane * 8);
        const float4* h1 = (const float4*)(h + (size_t)s1 * 256 + lane * 8);
        float4 v00 = h0[0], v01 = h0[1];
        float4 v10 = h1[0], v11 = h1[1];
        ssum += wt0 + wt1;
        acc0.x += wt0 * v00.x + wt1 * v10.x;
        acc0.y += wt0 * v00.y + wt1 * v10.y;
        acc0.z += wt0 * v00.z + wt1 * v10.z;
        acc0.w += wt0 * v00.w + wt1 * v10.w;
        acc1.x += wt0 * v01.x + wt1 * v11.x;
        acc1.y += wt0 * v01.y + wt1 * v11.y;
        acc1.z += wt0 * v01.z + wt1 * v11.z;
        acc1.w += wt0 * v01.w + wt1 * v11.w;
    }
    if (i < end) {
        int s0 = csr[i];
        float wt0 = __expf(lrelu(als[s0 * 4 + head] + aldv) - Mg);
        const float4* h0 = (const float4*)(h + (size_t)s0 * 256 + lane * 8);
        float4 v00 = h0[0], v01 = h0[1];
        ssum += wt0;
        acc0.x += wt0 * v00.x; acc0.y += wt0 * v00.y;
        acc0.z += wt0 * v00.z; acc0.w += wt0 * v00.w;
        acc1.x += wt0 * v01.x; acc1.y += wt0 * v01.y;
        acc1.z += wt0 * v01.z; acc1.w += wt0 * v01.w;
    }

    float inv = 1.f / (ssum + EPSV);
    float4 b0 = bias[lane * 2];
    float4 b1 = bias[lane * 2 + 1];
    float4 r0, r1;
    r0.x = fmaxf(acc0.x * inv + b0.x, 0.f);
    r0.y = fmaxf(acc0.y * inv + b0.y, 0.f);
    r0.z = fmaxf(acc0.z * inv + b0.z, 0.f);
    r0.w = fmaxf(acc0.w * inv + b0.w, 0.f);
    r1.x = fmaxf(acc1.x * inv + b1.x, 0.f);
    r1.y = fmaxf(acc1.y * inv + b1.y, 0.f);
    r1.z = fmaxf(acc1.z * inv + b1.z, 0.f);
    r1.w = fmaxf(acc1.w * inv + b1.w, 0.f);
    float4* op = (float4*)(out + (size_t)node * 256 + lane * 8);
    op[0] = r0;
    op[1] = r1;
}

// CSR gather-aggregate, H=1 C=64 (unroll-2)
__global__ void gat_agg1(const int* __restrict__ off, const int* __restrict__ csr,
                         const float* __restrict__ h,
                         const float* __restrict__ als, const float* __restrict__ ald,
                         float* __restrict__ out, int layer) {
    int node = (blockIdx.x * blockDim.x + threadIdx.x) >> 5;
    int lane = threadIdx.x & 31;
    if (node >= NN) return;

    float Mg = fmaxf(0.f, g_maxv[2 * layer] + g_maxv[2 * layer + 1]);
    float aldv = ald[node];

    float2 acc = make_float2(0.f, 0.f);
    float ssum = 0.f;

    int beg = off[node], end = off[node + 1];
    int i = beg;
    for (; i + 1 < end; i += 2) {
        int s0 = csr[i], s1 = csr[i + 1];
        float wt0 = __expf(lrelu(als[s0] + aldv) - Mg);
        float wt1 = __expf(lrelu(als[s1] + aldv) - Mg);
        float2 v0 = *(const float2*)(h + (size_t)s0 * 64 + lane * 2);
        float2 v1 = *(const float2*)(h + (size_t)s1 * 64 + lane * 2);
        ssum += wt0 + wt1;
        acc.x += wt0 * v0.x + wt1 * v1.x;
        acc.y += wt0 * v0.y + wt1 * v1.y;
    }
    if (i < end) {
        int s0 = csr[i];
        float wt0 = __expf(lrelu(als[s0] + aldv) - Mg);
        float2 v0 = *(const float2*)(h + (size_t)s0 * 64 + lane * 2);
        ssum += wt0;
        acc.x += wt0 * v0.x;
        acc.y += wt0 * v0.y;
    }

    float inv = 1.f / (ssum + EPSV);
    *(float2*)(out + (size_t)node * 64 + lane * 2) =
        make_float2(acc.x * inv, acc.y * inv);
}

// ----------------------------------------------------------------------------
// Pool + final
// ----------------------------------------------------------------------------
__global__ void zero_f4(float4* __restrict__ p, int n4) {
    int i = blockIdx.x * blockDim.x + threadIdx.x;
    int stride = gridDim.x * blockDim.x;
    float4 z = make_float4(0.f, 0.f, 0.f, 0.f);
    for (; i < n4; i += stride) p[i] = z;
}

__global__ void counts_k(const int* __restrict__ batch, float* __restrict__ cnt) {
    int g = threadIdx.x;
    if (g >= NGRAPH) return;
    int lo = 0, hi = NN;
    while (lo < hi) { int mid = (lo + hi) >> 1; if (batch[mid] < g) lo = mid + 1; else hi = mid; }
    int a = lo;
    lo = 0; hi = NN;
    while (lo < hi) { int mid = (lo + hi) >> 1; if (batch[mid] < g + 1) lo = mid + 1; else hi = mid; }
    cnt[g] = (float)(lo - a);
}

__global__ void pool_sum(const float* __restrict__ h, const int* __restrict__ batch,
                         float* __restrict__ pool) {
    int c = threadIdx.x & 63;
    int r = threadIdx.x >> 6;
    int start = blockIdx.x * 1024;
    int end = start + 1024;
    if (end > NN) end = NN;
    int cur = -1;
    float acc = 0.f;
    for (int nd = start + r; nd < end; nd += 4) {
        int g = batch[nd];
        if (g != cur) {
            if (cur >= 0) atomicAdd(&pool[cur * 64 + c], acc);
            cur = g;
            acc = 0.f;
        }
        acc += h[(size_t)nd * 64 + c];
    }
    if (cur >= 0) atomicAdd(&pool[cur * 64 + c], acc);
}

__global__ void final_k(const float* __restrict__ pool, const float* __restrict__ cnt,
                        const float* __restrict__ b3,
                        const float* __restrict__ linW, const float* __restrict__ linb,
                        float* __restrict__ out) {
    int g = blockIdx.x;
    int j = threadIdx.x;
    __shared__ float mean[64];
    float cc = fmaxf(cnt[g], 1.f);
    mean[j] = pool[g * 64 + j] / cc + b3[j];
    __syncthreads();
    float acc = 0.f;
#pragma unroll
    for (int k = 0; k < 64; k++) acc += mean[k] * linW[k * 64 + j];
    out[g * 64 + j] = acc + linb[j];
}

// ----------------------------------------------------------------------------
// Host launcher (layer-1 GEMM kept at the profiled stream slot)
// ----------------------------------------------------------------------------
extern "C" void kernel_launch(void* const* d_in, const int* in_sizes, int n_in,
                              void* d_out, int out_size) {
    const float* x     = (const float*)d_in[0];
    const void*  ei    = d_in[1];
    const void*  batch = d_in[3];
    const float* W1  = (const float*)d_in[4];
    const float* a1s = (const float*)d_in[5];
    const float* a1d = (const float*)d_in[6];
    const float* b1  = (const float*)d_in[7];
    const float* W2  = (const float*)d_in[8];
    const float* a2s = (const float*)d_in[9];
    const float* a2d = (const float*)d_in[10];
    const float* b2  = (const float*)d_in[11];
    const float* W3  = (const float*)d_in[12];
    const float* a3s = (const float*)d_in[13];
    const float* a3d = (const float*)d_in[14];
    const float* b3  = (const float*)d_in[15];
    const float* lW  = (const float*)d_in[16];
    const float* lb  = (const float*)d_in[17];
    float* out = (float*)d_out;

    float *p_h, *p_agg, *p_als, *p_ald, *p_pool, *p_cnt;
    int *p_src, *p_dst, *p_off, *p_cur, *p_csr, *p_batch;
    cudaGetSymbolAddress((void**)&p_h,    g_h);
    cudaGetSymbolAddress((void**)&p_agg,  g_agg);
    cudaGetSymbolAddress((void**)&p_als,  g_als);
    cudaGetSymbolAddress((void**)&p_ald,  g_ald);
    cudaGetSymbolAddress((void**)&p_src,  g_src);
    cudaGetSymbolAddress((void**)&p_dst,  g_dst);
    cudaGetSymbolAddress((void**)&p_off,  g_off);
    cudaGetSymbolAddress((void**)&p_cur,  g_cur);
    cudaGetSymbolAddress((void**)&p_csr,  g_csr);
    cudaGetSymbolAddress((void**)&p_batch,g_batch);
    cudaGetSymbolAddress((void**)&p_pool, g_pool);
    cudaGetSymbolAddress((void**)&p_cnt,  g_cnt);

    const int TB = 256;
    const int mTiles = (NN + 127) / 128;
    const int nodeWarpBlocks = (NN * 32 + TB - 1) / TB;

    detect_dtype<<<1, 32>>>((const unsigned int*)ei);                        // 0
    zero_i<<<(NN + 1 + TB - 1) / TB, TB>>>(p_off, NN + 1);                   // 1
    conv_edges<<<(NEDGE + TB - 1) / TB, TB>>>(ei, p_src, p_dst, p_off);      // 2

    // pos 3: layer-1 GEMM (profiled slot)
    {
        dim3 grid(mTiles, HC12 / 128);
        mma_gemm_fused<128, 4><<<grid, TB>>>(x, W1, p_h, NN, 128, HC12,
                                             a1s, a1d, p_als, p_ald, 0);     // 3
    }

    scan_k<<<1, 1024>>>(p_off, NN + 1);                                      // 4
    set_cursors<<<(NN + TB - 1) / TB, TB>>>(p_off, p_cur);                   // 5
    scatter_csr<<<(NEDGE + TB - 1) / TB, TB>>>(p_src, p_dst, p_cur, p_csr);  // 6
    conv_batch<<<(NN + TB - 1) / TB, TB>>>(batch, p_batch);                  // 7

    // ================= Layer 1 aggregation =================
    gat_agg4<<<nodeWarpBlocks, TB>>>(p_off, p_csr, p_h, p_als, p_ald,
                                     (const float4*)b1, p_agg, 0);

    // ================= Layer 2 =================
    {
        dim3 grid(mTiles, HC12 / 128);
        mma_gemm_fused<128, 4><<<grid, TB>>>(p_agg, W2, p_h, NN, HC12, HC12,
                                             a2s, a2d, p_als, p_ald, 1);
        gat_agg4<<<nodeWarpBlocks, TB>>>(p_off, p_csr, p_h, p_als, p_ald,
                                         (const float4*)b2, p_agg, 1);
    }

    // ================= Layer 3 =================
    {
        dim3 grid(mTiles, 1);
        mma_gemm_fused<64, 1><<<grid, TB>>>(p_agg, W3, p_h, NN, HC12, HC3,
                                            a3s, a3d, p_als, p_ald, 2);
        gat_agg1<<<nodeWarpBlocks, TB>>>(p_off, p_csr, p_h, p_als, p_ald, p_agg, 2);
    }

    // ================= Pool + final linear =================
    zero_f4<<<4, 64>>>((float4*)p_pool, NGRAPH * HC3 / 4);
    counts_k<<<1, 64>>>(p_batch, p_cnt);
    pool_sum<<<(NN + 1023) / 1024, 256>>>(p_agg, p_batch, p_pool);
    final_k<<<NGRAPH, 64>>>(p_pool, p_cnt, b3, lW, lb, out);
}